// round 7
// baseline (speedup 1.0000x reference)
#include <cuda_runtime.h>
#include <cuda_bf16.h>
#include <cstdint>

#define HEAD_NUM 8
#define DIM_QK 64
#define DIM_V 64
#define SPAN 64
#define STRIDE 4
#define R_SPAN 16

#define BATCH 2
#define MAX_LQ 4096
#define MAX_LKV 1024
#define DMODEL 512

// int8 two-digit layout: each row = 1024 bytes: [0:512)=d1, [512:1024)=d2
#define AROW 1024

// ---------------------------------------------------------------------------
// Scratch (no cudaMalloc allowed)
// ---------------------------------------------------------------------------
__device__ __align__(16) int8_t g_A8q[BATCH * MAX_LQ * AROW];     // q-act digits
__device__ __align__(16) int8_t g_A8k[BATCH * MAX_LKV * AROW];
__device__ __align__(16) int8_t g_A8v[BATCH * MAX_LKV * AROW];
__device__ __align__(16) int8_t g_A8c[BATCH * MAX_LQ * AROW];     // ctx digits
__device__ __align__(16) int8_t g_B8[4 * DMODEL * AROW];          // 4 weights (transposed) digits
__device__ __align__(16) float g_WT[4 * DMODEL * DMODEL];         // fp32 transposed weights
__device__ __align__(16) float g_sAq[BATCH * MAX_LQ];
__device__ __align__(16) float g_sAk[BATCH * MAX_LKV];
__device__ __align__(16) float g_sAv[BATCH * MAX_LKV];
__device__ __align__(16) float g_sAc[BATCH * MAX_LQ];
__device__ __align__(16) float g_sB[4 * DMODEL];
__device__ __align__(16) float g_Q[BATCH * MAX_LQ * DMODEL];
__device__ __align__(16) float g_K[BATCH * MAX_LKV * DMODEL];
__device__ __align__(16) float g_V[BATCH * MAX_LKV * DMODEL];
__device__ __align__(16) float g_ctx[BATCH * MAX_LQ * DMODEL];

// ---------------------------------------------------------------------------
// PTX helpers (baseline-target only)
// ---------------------------------------------------------------------------
__device__ __forceinline__ uint32_t smem_u32(const void* p) {
    uint32_t a;
    asm("{ .reg .u64 t; cvta.to.shared.u64 t, %1; cvt.u32.u64 %0, t; }" : "=r"(a) : "l"(p));
    return a;
}
__device__ __forceinline__ void cp_async16(uint32_t saddr, const void* gaddr) {
    asm volatile("cp.async.cg.shared.global [%0], [%1], 16;" :: "r"(saddr), "l"(gaddr));
}
__device__ __forceinline__ void cp_commit() { asm volatile("cp.async.commit_group;" ::: "memory"); }
__device__ __forceinline__ void cp_wait1() { asm volatile("cp.async.wait_group 1;" ::: "memory"); }
__device__ __forceinline__ void cp_wait0() { asm volatile("cp.async.wait_group 0;" ::: "memory"); }
__device__ __forceinline__ void ldm_x4(uint32_t* r, uint32_t addr) {
    asm volatile("ldmatrix.sync.aligned.m8n8.x4.shared.b16 {%0,%1,%2,%3}, [%4];"
                 : "=r"(r[0]), "=r"(r[1]), "=r"(r[2]), "=r"(r[3]) : "r"(addr));
}
__device__ __forceinline__ void ldm_x2(uint32_t* r, uint32_t addr) {
    asm volatile("ldmatrix.sync.aligned.m8n8.x2.shared.b16 {%0,%1}, [%2];"
                 : "=r"(r[0]), "=r"(r[1]) : "r"(addr));
}
// int8 MMA: m16n8k32 s8*s8 -> s32 (byte layout of frags identical to bf16 m16n8k16)
__device__ __forceinline__ void mma_s8(int* c, const uint32_t* a, const uint32_t* b) {
    asm volatile("mma.sync.aligned.m16n8k32.row.col.s32.s8.s8.s32 "
                 "{%0,%1,%2,%3}, {%4,%5,%6,%7}, {%8,%9}, {%0,%1,%2,%3};"
                 : "+r"(c[0]), "+r"(c[1]), "+r"(c[2]), "+r"(c[3])
                 : "r"(a[0]), "r"(a[1]), "r"(a[2]), "r"(a[3]), "r"(b[0]), "r"(b[1]));
}
__device__ __forceinline__ uint32_t sw128(uint32_t off) { return off ^ ((off >> 3) & 0x70); }

// ---------------------------------------------------------------------------
// int8 GEMM tile worker: CTA 128x128, 8 warps (2x4), warp tile 64x32.
// 12 k-chunks of 128 int8: 4x P11 (d1*d1), 8x Pmix (d1*d2 + d2*d1).
// 3-stage cp.async pipeline. smem tile rows = 128 bytes, sw128 swizzle.
// ---------------------------------------------------------------------------
#define STAGE_BYTES 32768u
#define GEMM_SMEM (3 * STAGE_BYTES)
#define NITER 12

__constant__ int c_ACH[NITER] = {0,1,2,3, 0,1,2,3, 4,5,6,7};
__constant__ int c_BCH[NITER] = {0,1,2,3, 4,5,6,7, 0,1,2,3};

__device__ __forceinline__ void issue_chunk8(const int8_t* __restrict__ A,
                                             const int8_t* __restrict__ B,
                                             uint32_t sb, int row0, int col0,
                                             int ac, int bc, int stage, int tid) {
    const uint32_t aoff = stage * STAGE_BYTES;
    const uint32_t boff = aoff + 16384u;
    #pragma unroll
    for (int p = 0; p < 4; p++) {
        const int idx = tid + p * 256;
        const int r = idx >> 3;
        const int c8 = idx & 7;
        const uint32_t sw = sw128((uint32_t)(r * 128 + c8 * 16));
        cp_async16(sb + aoff + sw, A + (size_t)(row0 + r) * AROW + ac * 128 + c8 * 16);
        cp_async16(sb + boff + sw, B + (size_t)(col0 + r) * AROW + bc * 128 + c8 * 16);
    }
    cp_commit();
}

__device__ __forceinline__ void gemm_tile_s8(const int8_t* __restrict__ A,
                                             const int8_t* __restrict__ B,
                                             const float* __restrict__ sA,
                                             const float* __restrict__ sB,
                                             float* __restrict__ C,
                                             int row0, int col0, uint32_t sb, int tid) {
    const int wid = tid >> 5, lane = tid & 31;
    const int warpM = wid >> 2, warpN = wid & 3;

    int acc[4][4][4];
    float f11[4][4][4];
    #pragma unroll
    for (int mi = 0; mi < 4; mi++)
        #pragma unroll
        for (int ni = 0; ni < 4; ni++)
            #pragma unroll
            for (int j = 0; j < 4; j++) acc[mi][ni][j] = 0;

    const int a_row_in_warp = lane & 15;
    const int a_khalf = (lane >> 4) & 1;
    const int b_row_in_tile = lane & 7;
    const int b_khalf = (lane >> 3) & 1;

    issue_chunk8(A, B, sb, row0, col0, c_ACH[0], c_BCH[0], 0, tid);
    issue_chunk8(A, B, sb, row0, col0, c_ACH[1], c_BCH[1], 1, tid);

    int stage = 0, nstage = 2;
    for (int i = 0; i < NITER; i++) {
        if (i + 1 < NITER) cp_wait1(); else cp_wait0();
        __syncthreads();

        if (i + 2 < NITER) {
            issue_chunk8(A, B, sb, row0, col0, c_ACH[i + 2], c_BCH[i + 2], nstage, tid);
            nstage = (nstage + 1 == 3) ? 0 : nstage + 1;
        }

        const uint32_t aoff = stage * STAGE_BYTES;
        const uint32_t boff = aoff + 16384u;
        #pragma unroll
        for (int kk = 0; kk < 4; kk++) {
            uint32_t afrag[4][4], bfrag[4][2];
            #pragma unroll
            for (int mi = 0; mi < 4; mi++) {
                const int r = warpM * 64 + mi * 16 + a_row_in_warp;
                ldm_x4(afrag[mi], sb + aoff + sw128((uint32_t)(r * 128 + kk * 32 + a_khalf * 16)));
            }
            #pragma unroll
            for (int ni = 0; ni < 4; ni++) {
                const int r = warpN * 32 + ni * 8 + b_row_in_tile;
                ldm_x2(bfrag[ni], sb + boff + sw128((uint32_t)(r * 128 + kk * 32 + b_khalf * 16)));
            }
            #pragma unroll
            for (int mi = 0; mi < 4; mi++)
                #pragma unroll
                for (int ni = 0; ni < 4; ni++)
                    mma_s8(acc[mi][ni], afrag[mi], bfrag[ni]);
        }
        stage = (stage + 1 == 3) ? 0 : stage + 1;

        if (i == 3) {   // end of P11 phase: stash and reset
            #pragma unroll
            for (int mi = 0; mi < 4; mi++)
                #pragma unroll
                for (int ni = 0; ni < 4; ni++)
                    #pragma unroll
                    for (int j = 0; j < 4; j++) {
                        f11[mi][ni][j] = (float)acc[mi][ni][j];
                        acc[mi][ni][j] = 0;
                    }
        }
    }

    const float invd = 1.f / 254.f;
    const int erow = lane >> 2;
    const int ecol = 2 * (lane & 3);
    #pragma unroll
    for (int mi = 0; mi < 4; mi++) {
        const int r = row0 + warpM * 64 + mi * 16 + erow;
        const float sa0 = __ldg(sA + r);
        const float sa1 = __ldg(sA + r + 8);
        #pragma unroll
        for (int ni = 0; ni < 4; ni++) {
            const int c = col0 + warpN * 32 + ni * 8 + ecol;
            const float sb0 = __ldg(sB + c);
            const float sb1 = __ldg(sB + c + 1);
            float v00 = sa0 * sb0 * (f11[mi][ni][0] + (float)acc[mi][ni][0] * invd);
            float v01 = sa0 * sb1 * (f11[mi][ni][1] + (float)acc[mi][ni][1] * invd);
            float v10 = sa1 * sb0 * (f11[mi][ni][2] + (float)acc[mi][ni][2] * invd);
            float v11 = sa1 * sb1 * (f11[mi][ni][3] + (float)acc[mi][ni][3] * invd);
            *(float2*)(C + (size_t)r * DMODEL + c) = make_float2(v00, v01);
            *(float2*)(C + (size_t)(r + 8) * DMODEL + c) = make_float2(v10, v11);
        }
    }
}

// Fused Q/K/V projection: 256 + 64 + 64 tiles linearized
__global__ __launch_bounds__(256, 1) void gemm_qkv_s8(const int8_t* __restrict__ Aq,
                                                      const int8_t* __restrict__ Ak,
                                                      const int8_t* __restrict__ Av,
                                                      const int8_t* __restrict__ B8,
                                                      const float* __restrict__ sAq,
                                                      const float* __restrict__ sAk,
                                                      const float* __restrict__ sAv,
                                                      const float* __restrict__ sB,
                                                      float* __restrict__ Cq,
                                                      float* __restrict__ Ck,
                                                      float* __restrict__ Cv) {
    extern __shared__ __align__(1024) char smem[];
    int t = blockIdx.x;
    const int8_t *A, *B;
    const float *sA, *sBw;
    float* C;
    if (t < 256) { A = Aq; B = B8; sA = sAq; sBw = sB; C = Cq; }
    else if (t < 320) { t -= 256; A = Ak; B = B8 + (size_t)DMODEL * AROW; sA = sAk; sBw = sB + DMODEL; C = Ck; }
    else { t -= 320; A = Av; B = B8 + 2 * (size_t)DMODEL * AROW; sA = sAv; sBw = sB + 2 * DMODEL; C = Cv; }
    gemm_tile_s8(A, B, sA, sBw, C, (t >> 2) * 128, (t & 3) * 128, smem_u32(smem), threadIdx.x);
}

__global__ __launch_bounds__(256, 1) void gemm_one_s8(const int8_t* __restrict__ A,
                                                      const int8_t* __restrict__ B,
                                                      const float* __restrict__ sA,
                                                      const float* __restrict__ sB,
                                                      float* __restrict__ C) {
    extern __shared__ __align__(1024) char smem[];
    gemm_tile_s8(A, B, sA, sB, C, blockIdx.y * 128, blockIdx.x * 128, smem_u32(smem), threadIdx.x);
}

// ---------------------------------------------------------------------------
// Weight transpose (fp32): WT[z][n][k] = W[z][k][n]
// ---------------------------------------------------------------------------
__global__ void transpose_W4(const float* __restrict__ W0, const float* __restrict__ W1,
                             const float* __restrict__ W2, const float* __restrict__ W3,
                             float* __restrict__ WT) {
    const float* W = (blockIdx.z == 0) ? W0 : (blockIdx.z == 1) ? W1 : (blockIdx.z == 2) ? W2 : W3;
    float* outW = WT + (size_t)blockIdx.z * DMODEL * DMODEL;
    __shared__ float t[32][33];
    const int k = blockIdx.y * 32 + threadIdx.y;
    const int n = blockIdx.x * 32 + threadIdx.x;
    t[threadIdx.y][threadIdx.x] = W[k * DMODEL + n];
    __syncthreads();
    const int n2 = blockIdx.x * 32 + threadIdx.y;
    const int k2 = blockIdx.y * 32 + threadIdx.x;
    outW[(size_t)n2 * DMODEL + k2] = t[threadIdx.x][threadIdx.y];
}

// ---------------------------------------------------------------------------
// Row quantization: row of 512 fp32 -> d1[512], d2[512] int8 + scale.
// x = s*(d1 + d2/254 + eps), s = rowmax/127. One warp per row.
// ---------------------------------------------------------------------------
__device__ __forceinline__ void quant_row_warp(const float* __restrict__ in,
                                               int8_t* __restrict__ out,
                                               float* __restrict__ scale,
                                               int row, int lane) {
    const float4* src = (const float4*)(in + (size_t)row * DMODEL);
    float4 x[4];
    float mx = 0.f;
    #pragma unroll
    for (int j = 0; j < 4; j++) {
        x[j] = __ldg(src + lane + 32 * j);
        mx = fmaxf(mx, fmaxf(fmaxf(fabsf(x[j].x), fabsf(x[j].y)),
                             fmaxf(fabsf(x[j].z), fabsf(x[j].w))));
    }
    #pragma unroll
    for (int off = 16; off > 0; off >>= 1)
        mx = fmaxf(mx, __shfl_xor_sync(0xffffffffu, mx, off));
    mx = fmaxf(mx, 1e-20f);
    const float inv = 127.f / mx;
    if (lane == 0) scale[row] = mx * (1.f / 127.f);
    uint32_t* o1 = (uint32_t*)(out + (size_t)row * AROW);
    uint32_t* o2 = o1 + 128;
    #pragma unroll
    for (int j = 0; j < 4; j++) {
        const float xs[4] = {x[j].x, x[j].y, x[j].z, x[j].w};
        uint32_t p1 = 0, p2 = 0;
        #pragma unroll
        for (int t = 0; t < 4; t++) {
            const float v = xs[t] * inv;
            const int a = __float2int_rn(v);
            const float e = v - (float)a;
            int bq = __float2int_rn(e * 254.f);
            bq = max(-127, min(127, bq));
            p1 |= (uint32_t)(a & 0xff) << (8 * t);
            p2 |= (uint32_t)(bq & 0xff) << (8 * t);
        }
        o1[lane + 32 * j] = p1;
        o2[lane + 32 * j] = p2;
    }
}

// generic: quantize nrows rows of `in`
__global__ __launch_bounds__(256) void quant_rows(const float* __restrict__ in,
                                                  int8_t* __restrict__ out,
                                                  float* __restrict__ scale, int nrows) {
    const int row = blockIdx.x * 8 + (threadIdx.x >> 5);
    if (row >= nrows) return;
    quant_row_warp(in, out, scale, row, threadIdx.x & 31);
}

// fused q/k/v input quantization
__global__ __launch_bounds__(256) void quant_qkv(const float* __restrict__ q,
                                                 const float* __restrict__ k,
                                                 const float* __restrict__ v,
                                                 int8_t* __restrict__ oq, int8_t* __restrict__ ok,
                                                 int8_t* __restrict__ ov,
                                                 float* __restrict__ sq, float* __restrict__ sk,
                                                 float* __restrict__ sv,
                                                 int Mq, int Mkv) {
    const int gw = blockIdx.x * 8 + (threadIdx.x >> 5);
    const int lane = threadIdx.x & 31;
    if (gw < Mq) quant_row_warp(q, oq, sq, gw, lane);
    else if (gw < Mq + Mkv) quant_row_warp(k, ok, sk, gw - Mq, lane);
    else if (gw < Mq + 2 * Mkv) quant_row_warp(v, ov, sv, gw - Mq - Mkv, lane);
}

// ---------------------------------------------------------------------------
// Sparse attention (R5 structure), fp32 ctx output
// ---------------------------------------------------------------------------
#define QBLK 128
#define CTILE 48

__device__ __forceinline__ int floordiv_s(int a, int d) {
    return (a >= 0) ? (a / d) : -((-a + d - 1) / d);
}

__global__ __launch_bounds__(256) void sparse_attn_v2(const float* __restrict__ Q,
                                                      const float* __restrict__ Kp,
                                                      const float* __restrict__ Vp,
                                                      float* __restrict__ ctx,
                                                      int Lq, int Lkv) {
    __shared__ float4 Ks4[CTILE][17];
    __shared__ float2 Vs2[CTILE][32];

    const int bh = blockIdx.y;
    const int b = bh / HEAD_NUM;
    const int h = bh % HEAD_NUM;
    const int c0 = blockIdx.x * QBLK;
    const int tid = threadIdx.x;
    const int wid = tid >> 5, lane = tid & 31;
    const int rlane = lane & 15;
    const int half = lane >> 4;

    const int colT0 = max(0, c0 / STRIDE - (R_SPAN - 1));

    for (int idx = tid; idx < CTILE * 16; idx += 256) {
        const int col = idx >> 4, d4 = idx & 15;
        if (colT0 + col < Lkv) {
            const size_t off = ((size_t)(b * Lkv + colT0 + col) * DMODEL) + h * 64 + d4 * 4;
            Ks4[col][d4] = __ldg((const float4*)(Kp + off));
        }
    }
    for (int idx = tid; idx < CTILE * 32; idx += 256) {
        const int col = idx >> 5, l2 = idx & 31;
        if (colT0 + col < Lkv) {
            const size_t off = ((size_t)(b * Lkv + colT0 + col) * DMODEL) + h * 64 + l2 * 2;
            Vs2[col][l2] = __ldg((const float2*)(Vp + off));
        }
    }
    __syncthreads();

    for (int step = 0; step < 8; step++) {
        const int cbase = c0 + wid * 16 + step * 2;
        const int c = cbase + half;

        const int fd = floordiv_s(SPAN - 1 - c, STRIDE);
        const int col = rlane - fd;
        const int row = c - STRIDE * col;
        const bool valid = (row >= 0) && (row < SPAN) && (col >= 0) && (col < Lkv);
        const int ii = min(max(col - colT0, 0), CTILE - 1);

        const float4* Qrow = (const float4*)(Q + ((size_t)(b * Lq + c) * DMODEL) + h * 64);
        float acc = 0.f;
        #pragma unroll
        for (int d4 = 0; d4 < 16; d4++) {
            const float4 qv = __ldg(Qrow + d4);
            const float4 kv = Ks4[ii][d4];
            acc += qv.x * kv.x + qv.y * kv.y + qv.z * kv.z + qv.w * kv.w;
        }
        const float sc = valid ? acc * 0.125f : -1e30f;

        float m = sc;
        #pragma unroll
        for (int off = 8; off > 0; off >>= 1)
            m = fmaxf(m, __shfl_xor_sync(0xffffffffu, m, off));
        const float e = valid ? __expf(sc - m) : 0.f;
        float s = e;
        #pragma unroll
        for (int off = 8; off > 0; off >>= 1)
            s += __shfl_xor_sync(0xffffffffu, s, off);
        const float w = e / s;

        #pragma unroll
        for (int qh = 0; qh < 2; qh++) {
            const int cq = cbase + qh;
            const int fdq = floordiv_s(SPAN - 1 - cq, STRIDE);
            float ox = 0.f, oy = 0.f;
            #pragma unroll
            for (int r = 0; r < R_SPAN; r++) {
                const float wr = __shfl_sync(0xffffffffu, w, qh * 16 + r);
                const int iir = min(max(r - fdq - colT0, 0), CTILE - 1);
                const float2 vv = Vs2[iir][lane];
                ox += wr * vv.x;
                oy += wr * vv.y;
            }
            float* base = ctx + (size_t)(b * Lq + cq) * DMODEL + h * DIM_V + 2 * lane;
            *(float2*)base = make_float2(ox, oy);
        }
    }
}

// ---------------------------------------------------------------------------
// Launch
// ---------------------------------------------------------------------------
extern "C" void kernel_launch(void* const* d_in, const int* in_sizes, int n_in,
                              void* d_out, int out_size) {
    const float* q    = (const float*)d_in[0];
    const float* k    = (const float*)d_in[1];
    const float* v    = (const float*)d_in[2];
    const float* Wq   = (const float*)d_in[3];
    const float* Wk   = (const float*)d_in[4];
    const float* Wv   = (const float*)d_in[5];
    const float* Wout = (const float*)d_in[6];
    float* out = (float*)d_out;

    const int Lq  = in_sizes[0] / (BATCH * DMODEL);   // 4096
    const int Lkv = in_sizes[1] / (BATCH * DMODEL);   // 1024
    const int Mq  = BATCH * Lq;    // 8192
    const int Mkv = BATCH * Lkv;   // 2048

    int8_t *gA8q, *gA8k, *gA8v, *gA8c, *gB8;
    float *gWT, *gsAq, *gsAk, *gsAv, *gsAc, *gsB, *gQ, *gK, *gV, *gctx;
    cudaGetSymbolAddress((void**)&gA8q, g_A8q);
    cudaGetSymbolAddress((void**)&gA8k, g_A8k);
    cudaGetSymbolAddress((void**)&gA8v, g_A8v);
    cudaGetSymbolAddress((void**)&gA8c, g_A8c);
    cudaGetSymbolAddress((void**)&gB8, g_B8);
    cudaGetSymbolAddress((void**)&gWT, g_WT);
    cudaGetSymbolAddress((void**)&gsAq, g_sAq);
    cudaGetSymbolAddress((void**)&gsAk, g_sAk);
    cudaGetSymbolAddress((void**)&gsAv, g_sAv);
    cudaGetSymbolAddress((void**)&gsAc, g_sAc);
    cudaGetSymbolAddress((void**)&gsB, g_sB);
    cudaGetSymbolAddress((void**)&gQ, g_Q);
    cudaGetSymbolAddress((void**)&gK, g_K);
    cudaGetSymbolAddress((void**)&gV, g_V);
    cudaGetSymbolAddress((void**)&gctx, g_ctx);

    cudaFuncSetAttribute(gemm_qkv_s8, cudaFuncAttributeMaxDynamicSharedMemorySize, GEMM_SMEM);
    cudaFuncSetAttribute(gemm_one_s8, cudaFuncAttributeMaxDynamicSharedMemorySize, GEMM_SMEM);

    // 1. transpose all weights (fp32)
    transpose_W4<<<dim3(16, 16, 4), dim3(32, 32)>>>(Wq, Wk, Wv, Wout, gWT);

    // 2. quantize weight rows (4*512 = 2048 rows)
    quant_rows<<<(4 * DMODEL + 7) / 8, 256>>>(gWT, gB8, gsB, 4 * DMODEL);

    // 3. quantize q/k/v activations
    const int totw = Mq + 2 * Mkv;
    quant_qkv<<<(totw + 7) / 8, 256>>>(q, k, v, gA8q, gA8k, gA8v, gsAq, gsAk, gsAv, Mq, Mkv);

    // 4. fused Q/K/V projection GEMM
    gemm_qkv_s8<<<384, 256, GEMM_SMEM>>>(gA8q, gA8k, gA8v, gB8, gsAq, gsAk, gsAv, gsB,
                                         gQ, gK, gV);

    // 5. sparse attention -> fp32 ctx
    sparse_attn_v2<<<dim3(Lq / QBLK, BATCH * HEAD_NUM), 256>>>(gQ, gK, gV, gctx, Lq, Lkv);

    // 6. quantize ctx rows
    quant_rows<<<(Mq + 7) / 8, 256>>>(gctx, gA8c, gsAc, Mq);

    // 7. out projection -> d_out
    gemm_one_s8<<<dim3(4, Mq / 128), 256, GEMM_SMEM>>>(gA8c, gB8 + 3 * (size_t)DMODEL * AROW,
                                                       gsAc, gsB + 3 * DMODEL, out);
}

// round 8
// speedup vs baseline: 4.0841x; 4.0841x over previous
#include <cuda_runtime.h>
#include <cuda_fp16.h>
#include <cstdint>

#define HEAD_NUM 8
#define DIM_QK 64
#define DIM_V 64
#define SPAN 64
#define STRIDE 4
#define R_SPAN 16

#define BATCH 2
#define MAX_LQ 4096
#define MAX_LKV 1024
#define DMODEL 512
#define GK 1024          // 2 * DMODEL (fp16 two-term split)
#define CHUNKS 16        // GK / 64
#define WSTRIDE (DMODEL * GK)

// ---------------------------------------------------------------------------
// Scratch (no cudaMalloc allowed)
// ---------------------------------------------------------------------------
__device__ __align__(16) __half g_Ab[BATCH * MAX_LQ * GK];    // q-split, then ctx-split
__device__ __align__(16) __half g_Kb[BATCH * MAX_LKV * GK];   // k-split
__device__ __align__(16) __half g_Vb[BATCH * MAX_LKV * GK];   // v-split
__device__ __align__(16) __half g_Wb4[4 * WSTRIDE];           // 4 weight splits (transposed)
__device__ __align__(16) float g_Q[BATCH * MAX_LQ * DMODEL];
__device__ __align__(16) float g_K[BATCH * MAX_LKV * DMODEL];
__device__ __align__(16) float g_V[BATCH * MAX_LKV * DMODEL];

// ---------------------------------------------------------------------------
// Baseline-target PTX helpers
// ---------------------------------------------------------------------------
__device__ __forceinline__ uint32_t smem_u32(const void* p) {
    uint32_t a;
    asm("{ .reg .u64 t; cvta.to.shared.u64 t, %1; cvt.u32.u64 %0, t; }" : "=r"(a) : "l"(p));
    return a;
}
__device__ __forceinline__ void cp_async16(uint32_t saddr, const void* gaddr) {
    asm volatile("cp.async.cg.shared.global [%0], [%1], 16;" :: "r"(saddr), "l"(gaddr));
}
__device__ __forceinline__ void cp_commit() { asm volatile("cp.async.commit_group;" ::: "memory"); }
__device__ __forceinline__ void cp_wait1() { asm volatile("cp.async.wait_group 1;" ::: "memory"); }
__device__ __forceinline__ void cp_wait0() { asm volatile("cp.async.wait_group 0;" ::: "memory"); }
__device__ __forceinline__ void ldm_x4(uint32_t* r, uint32_t addr) {
    asm volatile("ldmatrix.sync.aligned.m8n8.x4.shared.b16 {%0,%1,%2,%3}, [%4];"
                 : "=r"(r[0]), "=r"(r[1]), "=r"(r[2]), "=r"(r[3]) : "r"(addr));
}
__device__ __forceinline__ void ldm_x2(uint32_t* r, uint32_t addr) {
    asm volatile("ldmatrix.sync.aligned.m8n8.x2.shared.b16 {%0,%1}, [%2];"
                 : "=r"(r[0]), "=r"(r[1]) : "r"(addr));
}
__device__ __forceinline__ void mma_f16(float* c, const uint32_t* a, const uint32_t* b) {
    asm volatile("mma.sync.aligned.m16n8k16.row.col.f32.f16.f16.f32 "
                 "{%0,%1,%2,%3}, {%4,%5,%6,%7}, {%8,%9}, {%0,%1,%2,%3};"
                 : "+f"(c[0]), "+f"(c[1]), "+f"(c[2]), "+f"(c[3])
                 : "r"(a[0]), "r"(a[1]), "r"(a[2]), "r"(a[3]), "r"(b[0]), "r"(b[1]));
}
__device__ __forceinline__ uint32_t sw128(uint32_t off) { return off ^ ((off >> 3) & 0x70); }

// ---------------------------------------------------------------------------
// GEMM tile worker: C[128,128] += A'[row0.., GK] * Bt'[col0.., GK]^T
// 3-stage cp.async pipeline, one __syncthreads per K-chunk. 96 KB smem.
// ---------------------------------------------------------------------------
#define STAGE_BYTES 32768u
#define GEMM_SMEM (3 * STAGE_BYTES)

__device__ __forceinline__ void issue_chunk(const __half* __restrict__ A,
                                            const __half* __restrict__ Bt,
                                            uint32_t sb, int row0, int col0,
                                            int chunk, int stage, int tid) {
    const int k0 = chunk * 64;
    const uint32_t aoff = stage * STAGE_BYTES;
    const uint32_t boff = aoff + 16384u;
    #pragma unroll
    for (int p = 0; p < 4; p++) {
        const int idx = tid + p * 256;
        const int r = idx >> 3;
        const int c8 = idx & 7;
        const uint32_t sw = sw128((uint32_t)(r * 128 + c8 * 16));
        cp_async16(sb + aoff + sw, A + (size_t)(row0 + r) * GK + k0 + c8 * 8);
        cp_async16(sb + boff + sw, Bt + (size_t)(col0 + r) * GK + k0 + c8 * 8);
    }
    cp_commit();
}

__device__ __forceinline__ void gemm_tile(const __half* __restrict__ A,
                                          const __half* __restrict__ Bt,
                                          float* __restrict__ C,
                                          int row0, int col0, uint32_t sb, int tid) {
    const int wid = tid >> 5, lane = tid & 31;
    const int warpM = wid >> 2, warpN = wid & 3;

    float acc[4][4][4];
    #pragma unroll
    for (int mi = 0; mi < 4; mi++)
        #pragma unroll
        for (int ni = 0; ni < 4; ni++)
            #pragma unroll
            for (int j = 0; j < 4; j++) acc[mi][ni][j] = 0.f;

    const int a_row_in_warp = lane & 15;
    const int a_khalf = (lane >> 4) & 1;
    const int b_row_in_tile = lane & 7;
    const int b_khalf = (lane >> 3) & 1;

    issue_chunk(A, Bt, sb, row0, col0, 0, 0, tid);
    issue_chunk(A, Bt, sb, row0, col0, 1, 1, tid);

    int stage = 0, nstage = 2;
    for (int i = 0; i < CHUNKS; i++) {
        if (i + 1 < CHUNKS) cp_wait1(); else cp_wait0();
        __syncthreads();

        if (i + 2 < CHUNKS) {
            issue_chunk(A, Bt, sb, row0, col0, i + 2, nstage, tid);
            nstage = (nstage + 1 == 3) ? 0 : nstage + 1;
        }

        const uint32_t aoff = stage * STAGE_BYTES;
        const uint32_t boff = aoff + 16384u;
        #pragma unroll
        for (int kk = 0; kk < 4; kk++) {
            uint32_t afrag[4][4], bfrag[4][2];
            #pragma unroll
            for (int mi = 0; mi < 4; mi++) {
                const int r = warpM * 64 + mi * 16 + a_row_in_warp;
                ldm_x4(afrag[mi], sb + aoff + sw128((uint32_t)(r * 128 + kk * 32 + a_khalf * 16)));
            }
            #pragma unroll
            for (int ni = 0; ni < 4; ni++) {
                const int r = warpN * 32 + ni * 8 + b_row_in_tile;
                ldm_x2(bfrag[ni], sb + boff + sw128((uint32_t)(r * 128 + kk * 32 + b_khalf * 16)));
            }
            #pragma unroll
            for (int mi = 0; mi < 4; mi++)
                #pragma unroll
                for (int ni = 0; ni < 4; ni++)
                    mma_f16(acc[mi][ni], afrag[mi], bfrag[ni]);
        }
        stage = (stage + 1 == 3) ? 0 : stage + 1;
    }

    const int erow = lane >> 2;
    const int ecol = 2 * (lane & 3);
    #pragma unroll
    for (int mi = 0; mi < 4; mi++) {
        #pragma unroll
        for (int ni = 0; ni < 4; ni++) {
            const int r = row0 + warpM * 64 + mi * 16 + erow;
            const int c = col0 + warpN * 32 + ni * 8 + ecol;
            *(float2*)(C + (size_t)r * DMODEL + c) = make_float2(acc[mi][ni][0], acc[mi][ni][1]);
            *(float2*)(C + (size_t)(r + 8) * DMODEL + c) = make_float2(acc[mi][ni][2], acc[mi][ni][3]);
        }
    }
}

__global__ __launch_bounds__(256) void gemm_qkv(const __half* __restrict__ Aq,
                                                const __half* __restrict__ Ak,
                                                const __half* __restrict__ Av,
                                                const __half* __restrict__ Wb,
                                                float* __restrict__ Cq,
                                                float* __restrict__ Ck,
                                                float* __restrict__ Cv) {
    extern __shared__ __align__(1024) char smem[];
    int t = blockIdx.x;
    const __half *A, *B;
    float* C;
    if (t < 256) { A = Aq; B = Wb; C = Cq; }
    else if (t < 320) { t -= 256; A = Ak; B = Wb + WSTRIDE; C = Ck; }
    else { t -= 320; A = Av; B = Wb + 2 * WSTRIDE; C = Cv; }
    gemm_tile(A, B, C, (t >> 2) * 128, (t & 3) * 128, smem_u32(smem), threadIdx.x);
}

__global__ __launch_bounds__(256) void gemm_one(const __half* __restrict__ A,
                                                const __half* __restrict__ Bt,
                                                float* __restrict__ C) {
    extern __shared__ __align__(1024) char smem[];
    gemm_tile(A, Bt, C, blockIdx.y * 128, blockIdx.x * 128, smem_u32(smem), threadIdx.x);
}

// ---------------------------------------------------------------------------
// Split conversions (fp16 hi/lo)
// ---------------------------------------------------------------------------
struct __align__(8) hf4 { __half a, b, c, d; };

__device__ __forceinline__ void split1(float x, __half& h, __half& l) {
    h = __float2half(x);
    l = __float2half(x - __half2float(h));
}

// activations: out[m][k]=hi, out[m][512+k]=lo
__global__ __launch_bounds__(256) void split_act_all(const float4* __restrict__ q,
                                                     const float4* __restrict__ k,
                                                     const float4* __restrict__ v,
                                                     __half* __restrict__ outq,
                                                     __half* __restrict__ outk,
                                                     __half* __restrict__ outv,
                                                     int Mq, int Mkv) {
    const int gid = blockIdx.x * 256 + threadIdx.x;
    const int nq = Mq * 128, nkv = Mkv * 128;
    const float4* src;
    __half* out;
    int loc;
    if (gid < nq) { src = q; out = outq; loc = gid; }
    else if (gid < nq + nkv) { src = k; out = outk; loc = gid - nq; }
    else if (gid < nq + 2 * nkv) { src = v; out = outv; loc = gid - nq - nkv; }
    else return;
    const int m = loc >> 7, c4 = loc & 127;
    float4 x = src[loc];
    hf4 hv, lv;
    split1(x.x, hv.a, lv.a); split1(x.y, hv.b, lv.b);
    split1(x.z, hv.c, lv.c); split1(x.w, hv.d, lv.d);
    __half* base = out + (size_t)m * GK + c4 * 4;
    *(hf4*)(base) = hv;
    *(hf4*)(base + 512) = lv;
}

// weights (transpose + duplicate hi): Wb[n][k]=hi(W[k][n]), Wb[n][512+k]=hi
__global__ void split_wT_all(const float* __restrict__ W0, const float* __restrict__ W1,
                             const float* __restrict__ W2, const float* __restrict__ W3,
                             __half* __restrict__ Wb) {
    const float* W = (blockIdx.z == 0) ? W0 : (blockIdx.z == 1) ? W1 : (blockIdx.z == 2) ? W2 : W3;
    __half* outW = Wb + (size_t)blockIdx.z * WSTRIDE;
    __shared__ float t[32][33];
    const int k = blockIdx.y * 32 + threadIdx.y;
    const int n = blockIdx.x * 32 + threadIdx.x;
    t[threadIdx.y][threadIdx.x] = W[k * DMODEL + n];
    __syncthreads();
    const int n2 = blockIdx.x * 32 + threadIdx.y;
    const int k2 = blockIdx.y * 32 + threadIdx.x;
    const float x = t[threadIdx.x][threadIdx.y];
    const __half h = __float2half(x);
    __half* o = outW + (size_t)n2 * GK + k2;
    o[0] = h;
    o[512] = h;
}

// ---------------------------------------------------------------------------
// Sparse attention v2 (R5 structure), writes fp16 hi/lo ctx directly.
// ---------------------------------------------------------------------------
#define QBLK 128
#define CTILE 48

__device__ __forceinline__ int floordiv_s(int a, int d) {
    return (a >= 0) ? (a / d) : -((-a + d - 1) / d);
}

__global__ __launch_bounds__(256) void sparse_attn_v2(const float* __restrict__ Q,
                                                      const float* __restrict__ Kp,
                                                      const float* __restrict__ Vp,
                                                      __half* __restrict__ ctxh,
                                                      int Lq, int Lkv) {
    __shared__ float4 Ks4[CTILE][17];
    __shared__ float2 Vs2[CTILE][32];

    const int bh = blockIdx.y;
    const int b = bh / HEAD_NUM;
    const int h = bh % HEAD_NUM;
    const int c0 = blockIdx.x * QBLK;
    const int tid = threadIdx.x;
    const int wid = tid >> 5, lane = tid & 31;
    const int rlane = lane & 15;
    const int half = lane >> 4;

    const int colT0 = max(0, c0 / STRIDE - (R_SPAN - 1));

    for (int idx = tid; idx < CTILE * 16; idx += 256) {
        const int col = idx >> 4, d4 = idx & 15;
        if (colT0 + col < Lkv) {
            const size_t off = ((size_t)(b * Lkv + colT0 + col) * DMODEL) + h * 64 + d4 * 4;
            Ks4[col][d4] = __ldg((const float4*)(Kp + off));
        }
    }
    for (int idx = tid; idx < CTILE * 32; idx += 256) {
        const int col = idx >> 5, l2 = idx & 31;
        if (colT0 + col < Lkv) {
            const size_t off = ((size_t)(b * Lkv + colT0 + col) * DMODEL) + h * 64 + l2 * 2;
            Vs2[col][l2] = __ldg((const float2*)(Vp + off));
        }
    }
    __syncthreads();

    for (int step = 0; step < 8; step++) {
        const int cbase = c0 + wid * 16 + step * 2;
        const int c = cbase + half;

        const int fd = floordiv_s(SPAN - 1 - c, STRIDE);
        const int col = rlane - fd;
        const int row = c - STRIDE * col;
        const bool valid = (row >= 0) && (row < SPAN) && (col >= 0) && (col < Lkv);
        const int ii = min(max(col - colT0, 0), CTILE - 1);

        const float4* Qrow = (const float4*)(Q + ((size_t)(b * Lq + c) * DMODEL) + h * 64);
        float acc = 0.f;
        #pragma unroll
        for (int d4 = 0; d4 < 16; d4++) {
            const float4 qv = __ldg(Qrow + d4);
            const float4 kv = Ks4[ii][d4];
            acc += qv.x * kv.x + qv.y * kv.y + qv.z * kv.z + qv.w * kv.w;
        }
        const float sc = valid ? acc * 0.125f : -1e30f;

        float m = sc;
        #pragma unroll
        for (int off = 8; off > 0; off >>= 1)
            m = fmaxf(m, __shfl_xor_sync(0xffffffffu, m, off));
        const float e = valid ? __expf(sc - m) : 0.f;
        float s = e;
        #pragma unroll
        for (int off = 8; off > 0; off >>= 1)
            s += __shfl_xor_sync(0xffffffffu, s, off);
        const float w = e / s;

        #pragma unroll
        for (int qh = 0; qh < 2; qh++) {
            const int cq = cbase + qh;
            const int fdq = floordiv_s(SPAN - 1 - cq, STRIDE);
            float ox = 0.f, oy = 0.f;
            #pragma unroll
            for (int r = 0; r < R_SPAN; r++) {
                const float wr = __shfl_sync(0xffffffffu, w, qh * 16 + r);
                const int iir = min(max(r - fdq - colT0, 0), CTILE - 1);
                const float2 vv = Vs2[iir][lane];
                ox += wr * vv.x;
                oy += wr * vv.y;
            }
            __half hx, lx, hy, ly;
            split1(ox, hx, lx);
            split1(oy, hy, ly);
            __half* base = ctxh + (size_t)(b * Lq + cq) * GK + h * DIM_V + 2 * lane;
            __half2 hp; hp.x = hx; hp.y = hy;
            __half2 lp; lp.x = lx; lp.y = ly;
            *(__half2*)(base) = hp;
            *(__half2*)(base + 512) = lp;
        }
    }
}

// ---------------------------------------------------------------------------
// Launch
// ---------------------------------------------------------------------------
extern "C" void kernel_launch(void* const* d_in, const int* in_sizes, int n_in,
                              void* d_out, int out_size) {
    const float* q    = (const float*)d_in[0];
    const float* k    = (const float*)d_in[1];
    const float* v    = (const float*)d_in[2];
    const float* Wq   = (const float*)d_in[3];
    const float* Wk   = (const float*)d_in[4];
    const float* Wv   = (const float*)d_in[5];
    const float* Wout = (const float*)d_in[6];
    float* out = (float*)d_out;

    const int Lq  = in_sizes[0] / (BATCH * DMODEL);   // 4096
    const int Lkv = in_sizes[1] / (BATCH * DMODEL);   // 1024
    const int Mq  = BATCH * Lq;    // 8192
    const int Mkv = BATCH * Lkv;   // 2048

    __half *gAb, *gKb, *gVb, *gWb;
    float *gQ, *gK, *gV;
    cudaGetSymbolAddress((void**)&gAb, g_Ab);
    cudaGetSymbolAddress((void**)&gKb, g_Kb);
    cudaGetSymbolAddress((void**)&gVb, g_Vb);
    cudaGetSymbolAddress((void**)&gWb, g_Wb4);
    cudaGetSymbolAddress((void**)&gQ, g_Q);
    cudaGetSymbolAddress((void**)&gK, g_K);
    cudaGetSymbolAddress((void**)&gV, g_V);

    cudaFuncSetAttribute(gemm_qkv, cudaFuncAttributeMaxDynamicSharedMemorySize, GEMM_SMEM);
    cudaFuncSetAttribute(gemm_one, cudaFuncAttributeMaxDynamicSharedMemorySize, GEMM_SMEM);

    split_wT_all<<<dim3(16, 16, 4), dim3(32, 32)>>>(Wq, Wk, Wv, Wout, gWb);

    const int tot = (Mq + 2 * Mkv) * 128;
    split_act_all<<<(tot + 255) / 256, 256>>>((const float4*)q, (const float4*)k,
                                              (const float4*)v, gAb, gKb, gVb, Mq, Mkv);

    gemm_qkv<<<384, 256, GEMM_SMEM>>>(gAb, gKb, gVb, gWb, gQ, gK, gV);

    sparse_attn_v2<<<dim3(Lq / QBLK, BATCH * HEAD_NUM), 256>>>(gQ, gK, gV, gAb, Lq, Lkv);

    gemm_one<<<dim3(4, Mq / 128), 256, GEMM_SMEM>>>(gAb, gWb + 3 * (size_t)WSTRIDE, out);
}

// round 9
// speedup vs baseline: 5.6887x; 1.3929x over previous
#include <cuda_runtime.h>
#include <cuda_fp16.h>
#include <cstdint>

#define HEAD_NUM 8
#define DIM_QK 64
#define DIM_V 64
#define SPAN 64
#define STRIDE 4
#define R_SPAN 16

#define BATCH 2
#define MAX_LQ 4096
#define MAX_LKV 1024
#define DMODEL 512
#define GK 512           // single-rounded fp16 GEMM (no split terms)
#define CHUNKS 8         // GK / 64
#define WSTRIDE (DMODEL * GK)

// ---------------------------------------------------------------------------
// Scratch (no cudaMalloc allowed)
// ---------------------------------------------------------------------------
__device__ __align__(16) __half g_Ab[BATCH * MAX_LQ * GK];    // q fp16, then ctx fp16
__device__ __align__(16) __half g_Kb[BATCH * MAX_LKV * GK];   // k fp16
__device__ __align__(16) __half g_Vb[BATCH * MAX_LKV * GK];   // v fp16
__device__ __align__(16) __half g_Wb4[4 * WSTRIDE];           // 4 weights (transposed) fp16
__device__ __align__(16) float g_Q[BATCH * MAX_LQ * DMODEL];
__device__ __align__(16) float g_K[BATCH * MAX_LKV * DMODEL];
__device__ __align__(16) float g_V[BATCH * MAX_LKV * DMODEL];

// ---------------------------------------------------------------------------
// Baseline-target PTX helpers
// ---------------------------------------------------------------------------
__device__ __forceinline__ uint32_t smem_u32(const void* p) {
    uint32_t a;
    asm("{ .reg .u64 t; cvta.to.shared.u64 t, %1; cvt.u32.u64 %0, t; }" : "=r"(a) : "l"(p));
    return a;
}
__device__ __forceinline__ void cp_async16(uint32_t saddr, const void* gaddr) {
    asm volatile("cp.async.cg.shared.global [%0], [%1], 16;" :: "r"(saddr), "l"(gaddr));
}
__device__ __forceinline__ void cp_commit() { asm volatile("cp.async.commit_group;" ::: "memory"); }
__device__ __forceinline__ void cp_wait1() { asm volatile("cp.async.wait_group 1;" ::: "memory"); }
__device__ __forceinline__ void cp_wait0() { asm volatile("cp.async.wait_group 0;" ::: "memory"); }
__device__ __forceinline__ void ldm_x4(uint32_t* r, uint32_t addr) {
    asm volatile("ldmatrix.sync.aligned.m8n8.x4.shared.b16 {%0,%1,%2,%3}, [%4];"
                 : "=r"(r[0]), "=r"(r[1]), "=r"(r[2]), "=r"(r[3]) : "r"(addr));
}
__device__ __forceinline__ void ldm_x2(uint32_t* r, uint32_t addr) {
    asm volatile("ldmatrix.sync.aligned.m8n8.x2.shared.b16 {%0,%1}, [%2];"
                 : "=r"(r[0]), "=r"(r[1]) : "r"(addr));
}
__device__ __forceinline__ void mma_f16(float* c, const uint32_t* a, const uint32_t* b) {
    asm volatile("mma.sync.aligned.m16n8k16.row.col.f32.f16.f16.f32 "
                 "{%0,%1,%2,%3}, {%4,%5,%6,%7}, {%8,%9}, {%0,%1,%2,%3};"
                 : "+f"(c[0]), "+f"(c[1]), "+f"(c[2]), "+f"(c[3])
                 : "r"(a[0]), "r"(a[1]), "r"(a[2]), "r"(a[3]), "r"(b[0]), "r"(b[1]));
}
__device__ __forceinline__ uint32_t sw128(uint32_t off) { return off ^ ((off >> 3) & 0x70); }

// ---------------------------------------------------------------------------
// GEMM tile worker: C[128,128] += A[row0.., GK] * Bt[col0.., GK]^T
// 3-stage cp.async pipeline, one __syncthreads per K-chunk.
// ---------------------------------------------------------------------------
#define STAGE_BYTES 32768u
#define GEMM_SMEM (3 * STAGE_BYTES)

__device__ __forceinline__ void issue_chunk(const __half* __restrict__ A,
                                            const __half* __restrict__ Bt,
                                            uint32_t sb, int row0, int col0,
                                            int chunk, int stage, int tid) {
    const int k0 = chunk * 64;
    const uint32_t aoff = stage * STAGE_BYTES;
    const uint32_t boff = aoff + 16384u;
    #pragma unroll
    for (int p = 0; p < 4; p++) {
        const int idx = tid + p * 256;
        const int r = idx >> 3;
        const int c8 = idx & 7;
        const uint32_t sw = sw128((uint32_t)(r * 128 + c8 * 16));
        cp_async16(sb + aoff + sw, A + (size_t)(row0 + r) * GK + k0 + c8 * 8);
        cp_async16(sb + boff + sw, Bt + (size_t)(col0 + r) * GK + k0 + c8 * 8);
    }
    cp_commit();
}

__device__ __forceinline__ void gemm_tile(const __half* __restrict__ A,
                                          const __half* __restrict__ Bt,
                                          float* __restrict__ C,
                                          int row0, int col0, uint32_t sb, int tid) {
    const int wid = tid >> 5, lane = tid & 31;
    const int warpM = wid >> 2, warpN = wid & 3;

    float acc[4][4][4];
    #pragma unroll
    for (int mi = 0; mi < 4; mi++)
        #pragma unroll
        for (int ni = 0; ni < 4; ni++)
            #pragma unroll
            for (int j = 0; j < 4; j++) acc[mi][ni][j] = 0.f;

    const int a_row_in_warp = lane & 15;
    const int a_khalf = (lane >> 4) & 1;
    const int b_row_in_tile = lane & 7;
    const int b_khalf = (lane >> 3) & 1;

    issue_chunk(A, Bt, sb, row0, col0, 0, 0, tid);
    issue_chunk(A, Bt, sb, row0, col0, 1, 1, tid);

    int stage = 0, nstage = 2;
    for (int i = 0; i < CHUNKS; i++) {
        if (i + 1 < CHUNKS) cp_wait1(); else cp_wait0();
        __syncthreads();

        if (i + 2 < CHUNKS) {
            issue_chunk(A, Bt, sb, row0, col0, i + 2, nstage, tid);
            nstage = (nstage + 1 == 3) ? 0 : nstage + 1;
        }

        const uint32_t aoff = stage * STAGE_BYTES;
        const uint32_t boff = aoff + 16384u;
        #pragma unroll
        for (int kk = 0; kk < 4; kk++) {
            uint32_t afrag[4][4], bfrag[4][2];
            #pragma unroll
            for (int mi = 0; mi < 4; mi++) {
                const int r = warpM * 64 + mi * 16 + a_row_in_warp;
                ldm_x4(afrag[mi], sb + aoff + sw128((uint32_t)(r * 128 + kk * 32 + a_khalf * 16)));
            }
            #pragma unroll
            for (int ni = 0; ni < 4; ni++) {
                const int r = warpN * 32 + ni * 8 + b_row_in_tile;
                ldm_x2(bfrag[ni], sb + boff + sw128((uint32_t)(r * 128 + kk * 32 + b_khalf * 16)));
            }
            #pragma unroll
            for (int mi = 0; mi < 4; mi++)
                #pragma unroll
                for (int ni = 0; ni < 4; ni++)
                    mma_f16(acc[mi][ni], afrag[mi], bfrag[ni]);
        }
        stage = (stage + 1 == 3) ? 0 : stage + 1;
    }

    const int erow = lane >> 2;
    const int ecol = 2 * (lane & 3);
    #pragma unroll
    for (int mi = 0; mi < 4; mi++) {
        #pragma unroll
        for (int ni = 0; ni < 4; ni++) {
            const int r = row0 + warpM * 64 + mi * 16 + erow;
            const int c = col0 + warpN * 32 + ni * 8 + ecol;
            *(float2*)(C + (size_t)r * DMODEL + c) = make_float2(acc[mi][ni][0], acc[mi][ni][1]);
            *(float2*)(C + (size_t)(r + 8) * DMODEL + c) = make_float2(acc[mi][ni][2], acc[mi][ni][3]);
        }
    }
}

__global__ __launch_bounds__(256) void gemm_qkv(const __half* __restrict__ Aq,
                                                const __half* __restrict__ Ak,
                                                const __half* __restrict__ Av,
                                                const __half* __restrict__ Wb,
                                                float* __restrict__ Cq,
                                                float* __restrict__ Ck,
                                                float* __restrict__ Cv) {
    extern __shared__ __align__(1024) char smem[];
    int t = blockIdx.x;
    const __half *A, *B;
    float* C;
    if (t < 256) { A = Aq; B = Wb; C = Cq; }
    else if (t < 320) { t -= 256; A = Ak; B = Wb + WSTRIDE; C = Ck; }
    else { t -= 320; A = Av; B = Wb + 2 * WSTRIDE; C = Cv; }
    gemm_tile(A, B, C, (t >> 2) * 128, (t & 3) * 128, smem_u32(smem), threadIdx.x);
}

__global__ __launch_bounds__(256) void gemm_one(const __half* __restrict__ A,
                                                const __half* __restrict__ Bt,
                                                float* __restrict__ C) {
    extern __shared__ __align__(1024) char smem[];
    gemm_tile(A, Bt, C, blockIdx.y * 128, blockIdx.x * 128, smem_u32(smem), threadIdx.x);
}

// ---------------------------------------------------------------------------
// fp16 conversions
// ---------------------------------------------------------------------------
struct __align__(8) hf4 { __half a, b, c, d; };

__global__ __launch_bounds__(256) void cvt_act_all(const float4* __restrict__ q,
                                                   const float4* __restrict__ k,
                                                   const float4* __restrict__ v,
                                                   __half* __restrict__ outq,
                                                   __half* __restrict__ outk,
                                                   __half* __restrict__ outv,
                                                   int Mq, int Mkv) {
    const int gid = blockIdx.x * 256 + threadIdx.x;
    const int nq = Mq * 128, nkv = Mkv * 128;
    const float4* src;
    __half* out;
    int loc;
    if (gid < nq) { src = q; out = outq; loc = gid; }
    else if (gid < nq + nkv) { src = k; out = outk; loc = gid - nq; }
    else if (gid < nq + 2 * nkv) { src = v; out = outv; loc = gid - nq - nkv; }
    else return;
    float4 x = src[loc];
    hf4 hv;
    hv.a = __float2half(x.x); hv.b = __float2half(x.y);
    hv.c = __float2half(x.z); hv.d = __float2half(x.w);
    *(hf4*)(out + (size_t)loc * 4) = hv;
}

// weights: transpose + round. Wb[n][k] = fp16(W[k][n])
__global__ void cvt_wT_all(const float* __restrict__ W0, const float* __restrict__ W1,
                           const float* __restrict__ W2, const float* __restrict__ W3,
                           __half* __restrict__ Wb) {
    const float* W = (blockIdx.z == 0) ? W0 : (blockIdx.z == 1) ? W1 : (blockIdx.z == 2) ? W2 : W3;
    __half* outW = Wb + (size_t)blockIdx.z * WSTRIDE;
    __shared__ float t[32][33];
    const int k = blockIdx.y * 32 + threadIdx.y;
    const int n = blockIdx.x * 32 + threadIdx.x;
    t[threadIdx.y][threadIdx.x] = W[k * DMODEL + n];
    __syncthreads();
    const int n2 = blockIdx.x * 32 + threadIdx.y;
    const int k2 = blockIdx.y * 32 + threadIdx.x;
    outW[(size_t)n2 * GK + k2] = __float2half(t[threadIdx.x][threadIdx.y]);
}

// ---------------------------------------------------------------------------
// Sparse attention v2 (R5 structure), writes fp16 ctx directly.
// ---------------------------------------------------------------------------
#define QBLK 128
#define CTILE 48

__device__ __forceinline__ int floordiv_s(int a, int d) {
    return (a >= 0) ? (a / d) : -((-a + d - 1) / d);
}

__global__ __launch_bounds__(256) void sparse_attn_v2(const float* __restrict__ Q,
                                                      const float* __restrict__ Kp,
                                                      const float* __restrict__ Vp,
                                                      __half* __restrict__ ctxh,
                                                      int Lq, int Lkv) {
    __shared__ float4 Ks4[CTILE][17];
    __shared__ float2 Vs2[CTILE][32];

    const int bh = blockIdx.y;
    const int b = bh / HEAD_NUM;
    const int h = bh % HEAD_NUM;
    const int c0 = blockIdx.x * QBLK;
    const int tid = threadIdx.x;
    const int wid = tid >> 5, lane = tid & 31;
    const int rlane = lane & 15;
    const int half = lane >> 4;

    const int colT0 = max(0, c0 / STRIDE - (R_SPAN - 1));

    for (int idx = tid; idx < CTILE * 16; idx += 256) {
        const int col = idx >> 4, d4 = idx & 15;
        if (colT0 + col < Lkv) {
            const size_t off = ((size_t)(b * Lkv + colT0 + col) * DMODEL) + h * 64 + d4 * 4;
            Ks4[col][d4] = __ldg((const float4*)(Kp + off));
        }
    }
    for (int idx = tid; idx < CTILE * 32; idx += 256) {
        const int col = idx >> 5, l2 = idx & 31;
        if (colT0 + col < Lkv) {
            const size_t off = ((size_t)(b * Lkv + colT0 + col) * DMODEL) + h * 64 + l2 * 2;
            Vs2[col][l2] = __ldg((const float2*)(Vp + off));
        }
    }
    __syncthreads();

    for (int step = 0; step < 8; step++) {
        const int cbase = c0 + wid * 16 + step * 2;
        const int c = cbase + half;

        const int fd = floordiv_s(SPAN - 1 - c, STRIDE);
        const int col = rlane - fd;
        const int row = c - STRIDE * col;
        const bool valid = (row >= 0) && (row < SPAN) && (col >= 0) && (col < Lkv);
        const int ii = min(max(col - colT0, 0), CTILE - 1);

        const float4* Qrow = (const float4*)(Q + ((size_t)(b * Lq + c) * DMODEL) + h * 64);
        float acc = 0.f;
        #pragma unroll
        for (int d4 = 0; d4 < 16; d4++) {
            const float4 qv = __ldg(Qrow + d4);
            const float4 kv = Ks4[ii][d4];
            acc += qv.x * kv.x + qv.y * kv.y + qv.z * kv.z + qv.w * kv.w;
        }
        const float sc = valid ? acc * 0.125f : -1e30f;

        float m = sc;
        #pragma unroll
        for (int off = 8; off > 0; off >>= 1)
            m = fmaxf(m, __shfl_xor_sync(0xffffffffu, m, off));
        const float e = valid ? __expf(sc - m) : 0.f;
        float s = e;
        #pragma unroll
        for (int off = 8; off > 0; off >>= 1)
            s += __shfl_xor_sync(0xffffffffu, s, off);
        const float w = e / s;

        #pragma unroll
        for (int qh = 0; qh < 2; qh++) {
            const int cq = cbase + qh;
            const int fdq = floordiv_s(SPAN - 1 - cq, STRIDE);
            float ox = 0.f, oy = 0.f;
            #pragma unroll
            for (int r = 0; r < R_SPAN; r++) {
                const float wr = __shfl_sync(0xffffffffu, w, qh * 16 + r);
                const int iir = min(max(r - fdq - colT0, 0), CTILE - 1);
                const float2 vv = Vs2[iir][lane];
                ox += wr * vv.x;
                oy += wr * vv.y;
            }
            __half2 hp;
            hp.x = __float2half(ox);
            hp.y = __float2half(oy);
            *(__half2*)(ctxh + (size_t)(b * Lq + cq) * GK + h * DIM_V + 2 * lane) = hp;
        }
    }
}

// ---------------------------------------------------------------------------
// Launch
// ---------------------------------------------------------------------------
extern "C" void kernel_launch(void* const* d_in, const int* in_sizes, int n_in,
                              void* d_out, int out_size) {
    const float* q    = (const float*)d_in[0];
    const float* k    = (const float*)d_in[1];
    const float* v    = (const float*)d_in[2];
    const float* Wq   = (const float*)d_in[3];
    const float* Wk   = (const float*)d_in[4];
    const float* Wv   = (const float*)d_in[5];
    const float* Wout = (const float*)d_in[6];
    float* out = (float*)d_out;

    const int Lq  = in_sizes[0] / (BATCH * DMODEL);   // 4096
    const int Lkv = in_sizes[1] / (BATCH * DMODEL);   // 1024
    const int Mq  = BATCH * Lq;    // 8192
    const int Mkv = BATCH * Lkv;   // 2048

    __half *gAb, *gKb, *gVb, *gWb;
    float *gQ, *gK, *gV;
    cudaGetSymbolAddress((void**)&gAb, g_Ab);
    cudaGetSymbolAddress((void**)&gKb, g_Kb);
    cudaGetSymbolAddress((void**)&gVb, g_Vb);
    cudaGetSymbolAddress((void**)&gWb, g_Wb4);
    cudaGetSymbolAddress((void**)&gQ, g_Q);
    cudaGetSymbolAddress((void**)&gK, g_K);
    cudaGetSymbolAddress((void**)&gV, g_V);

    cudaFuncSetAttribute(gemm_qkv, cudaFuncAttributeMaxDynamicSharedMemorySize, GEMM_SMEM);
    cudaFuncSetAttribute(gemm_one, cudaFuncAttributeMaxDynamicSharedMemorySize, GEMM_SMEM);

    cvt_wT_all<<<dim3(16, 16, 4), dim3(32, 32)>>>(Wq, Wk, Wv, Wout, gWb);

    const int tot = (Mq + 2 * Mkv) * 128;
    cvt_act_all<<<(tot + 255) / 256, 256>>>((const float4*)q, (const float4*)k,
                                            (const float4*)v, gAb, gKb, gVb, Mq, Mkv);

    gemm_qkv<<<384, 256, GEMM_SMEM>>>(gAb, gKb, gVb, gWb, gQ, gK, gV);

    sparse_attn_v2<<<dim3(Lq / QBLK, BATCH * HEAD_NUM), 256>>>(gQ, gK, gV, gAb, Lq, Lkv);

    gemm_one<<<dim3(4, Mq / 128), 256, GEMM_SMEM>>>(gAb, gWb + 3 * (size_t)WSTRIDE, out);
}

// round 10
// speedup vs baseline: 5.8297x; 1.0248x over previous
#include <cuda_runtime.h>
#include <cuda_fp16.h>
#include <cstdint>

#define HEAD_NUM 8
#define DIM_QK 64
#define DIM_V 64
#define SPAN 64
#define STRIDE 4
#define R_SPAN 16

#define BATCH 2
#define MAX_LQ 4096
#define MAX_LKV 1024
#define DMODEL 512
#define GK 512           // single-rounded fp16 GEMM
#define CHUNKS 8         // GK / 64
#define WSTRIDE (DMODEL * GK)

// ---------------------------------------------------------------------------
// Scratch (no cudaMalloc allowed)
// ---------------------------------------------------------------------------
__device__ __align__(16) __half g_Ab[BATCH * MAX_LQ * GK];    // q fp16, then ctx fp16
__device__ __align__(16) __half g_Kb[BATCH * MAX_LKV * GK];   // k fp16
__device__ __align__(16) __half g_Vb[BATCH * MAX_LKV * GK];   // v fp16
__device__ __align__(16) __half g_Wb4[4 * WSTRIDE];           // 4 weights (transposed) fp16
__device__ __align__(16) float g_Q[BATCH * MAX_LQ * DMODEL];
__device__ __align__(16) float g_K[BATCH * MAX_LKV * DMODEL];
__device__ __align__(16) float g_V[BATCH * MAX_LKV * DMODEL];

// ---------------------------------------------------------------------------
// Baseline-target PTX helpers
// ---------------------------------------------------------------------------
__device__ __forceinline__ uint32_t smem_u32(const void* p) {
    uint32_t a;
    asm("{ .reg .u64 t; cvta.to.shared.u64 t, %1; cvt.u32.u64 %0, t; }" : "=r"(a) : "l"(p));
    return a;
}
__device__ __forceinline__ void cp_async16(uint32_t saddr, const void* gaddr) {
    asm volatile("cp.async.cg.shared.global [%0], [%1], 16;" :: "r"(saddr), "l"(gaddr));
}
__device__ __forceinline__ void cp_commit() { asm volatile("cp.async.commit_group;" ::: "memory"); }
__device__ __forceinline__ void cp_wait1() { asm volatile("cp.async.wait_group 1;" ::: "memory"); }
__device__ __forceinline__ void cp_wait0() { asm volatile("cp.async.wait_group 0;" ::: "memory"); }
__device__ __forceinline__ void ldm_x4(uint32_t* r, uint32_t addr) {
    asm volatile("ldmatrix.sync.aligned.m8n8.x4.shared.b16 {%0,%1,%2,%3}, [%4];"
                 : "=r"(r[0]), "=r"(r[1]), "=r"(r[2]), "=r"(r[3]) : "r"(addr));
}
__device__ __forceinline__ void ldm_x2(uint32_t* r, uint32_t addr) {
    asm volatile("ldmatrix.sync.aligned.m8n8.x2.shared.b16 {%0,%1}, [%2];"
                 : "=r"(r[0]), "=r"(r[1]) : "r"(addr));
}
__device__ __forceinline__ void mma_f16(float* c, const uint32_t* a, const uint32_t* b) {
    asm volatile("mma.sync.aligned.m16n8k16.row.col.f32.f16.f16.f32 "
                 "{%0,%1,%2,%3}, {%4,%5,%6,%7}, {%8,%9}, {%0,%1,%2,%3};"
                 : "+f"(c[0]), "+f"(c[1]), "+f"(c[2]), "+f"(c[3])
                 : "r"(a[0]), "r"(a[1]), "r"(a[2]), "r"(a[3]), "r"(b[0]), "r"(b[1]));
}
__device__ __forceinline__ uint32_t sw128(uint32_t off) { return off ^ ((off >> 3) & 0x70); }

// ---------------------------------------------------------------------------
// GEMM tile worker: C[128,128] += A[row0.., GK] * Bt[col0.., GK]^T
// 3-stage cp.async pipeline, one __syncthreads per K-chunk.
// ---------------------------------------------------------------------------
#define STAGE_BYTES 32768u
#define GEMM_SMEM (3 * STAGE_BYTES)

__device__ __forceinline__ void issue_chunk(const __half* __restrict__ A,
                                            const __half* __restrict__ Bt,
                                            uint32_t sb, int row0, int col0,
                                            int chunk, int stage, int tid) {
    const int k0 = chunk * 64;
    const uint32_t aoff = stage * STAGE_BYTES;
    const uint32_t boff = aoff + 16384u;
    #pragma unroll
    for (int p = 0; p < 4; p++) {
        const int idx = tid + p * 256;
        const int r = idx >> 3;
        const int c8 = idx & 7;
        const uint32_t sw = sw128((uint32_t)(r * 128 + c8 * 16));
        cp_async16(sb + aoff + sw, A + (size_t)(row0 + r) * GK + k0 + c8 * 8);
        cp_async16(sb + boff + sw, Bt + (size_t)(col0 + r) * GK + k0 + c8 * 8);
    }
    cp_commit();
}

__device__ __forceinline__ void gemm_tile(const __half* __restrict__ A,
                                          const __half* __restrict__ Bt,
                                          float* __restrict__ C,
                                          int row0, int col0, uint32_t sb, int tid) {
    const int wid = tid >> 5, lane = tid & 31;
    const int warpM = wid >> 2, warpN = wid & 3;

    float acc[4][4][4];
    #pragma unroll
    for (int mi = 0; mi < 4; mi++)
        #pragma unroll
        for (int ni = 0; ni < 4; ni++)
            #pragma unroll
            for (int j = 0; j < 4; j++) acc[mi][ni][j] = 0.f;

    const int a_row_in_warp = lane & 15;
    const int a_khalf = (lane >> 4) & 1;
    const int b_row_in_tile = lane & 7;
    const int b_khalf = (lane >> 3) & 1;

    issue_chunk(A, Bt, sb, row0, col0, 0, 0, tid);
    issue_chunk(A, Bt, sb, row0, col0, 1, 1, tid);

    int stage = 0, nstage = 2;
    for (int i = 0; i < CHUNKS; i++) {
        if (i + 1 < CHUNKS) cp_wait1(); else cp_wait0();
        __syncthreads();

        if (i + 2 < CHUNKS) {
            issue_chunk(A, Bt, sb, row0, col0, i + 2, nstage, tid);
            nstage = (nstage + 1 == 3) ? 0 : nstage + 1;
        }

        const uint32_t aoff = stage * STAGE_BYTES;
        const uint32_t boff = aoff + 16384u;
        #pragma unroll
        for (int kk = 0; kk < 4; kk++) {
            uint32_t afrag[4][4], bfrag[4][2];
            #pragma unroll
            for (int mi = 0; mi < 4; mi++) {
                const int r = warpM * 64 + mi * 16 + a_row_in_warp;
                ldm_x4(afrag[mi], sb + aoff + sw128((uint32_t)(r * 128 + kk * 32 + a_khalf * 16)));
            }
            #pragma unroll
            for (int ni = 0; ni < 4; ni++) {
                const int r = warpN * 32 + ni * 8 + b_row_in_tile;
                ldm_x2(bfrag[ni], sb + boff + sw128((uint32_t)(r * 128 + kk * 32 + b_khalf * 16)));
            }
            #pragma unroll
            for (int mi = 0; mi < 4; mi++)
                #pragma unroll
                for (int ni = 0; ni < 4; ni++)
                    mma_f16(acc[mi][ni], afrag[mi], bfrag[ni]);
        }
        stage = (stage + 1 == 3) ? 0 : stage + 1;
    }

    const int erow = lane >> 2;
    const int ecol = 2 * (lane & 3);
    #pragma unroll
    for (int mi = 0; mi < 4; mi++) {
        #pragma unroll
        for (int ni = 0; ni < 4; ni++) {
            const int r = row0 + warpM * 64 + mi * 16 + erow;
            const int c = col0 + warpN * 32 + ni * 8 + ecol;
            *(float2*)(C + (size_t)r * DMODEL + c) = make_float2(acc[mi][ni][0], acc[mi][ni][1]);
            *(float2*)(C + (size_t)(r + 8) * DMODEL + c) = make_float2(acc[mi][ni][2], acc[mi][ni][3]);
        }
    }
}

__global__ __launch_bounds__(256) void gemm_qkv(const __half* __restrict__ Aq,
                                                const __half* __restrict__ Ak,
                                                const __half* __restrict__ Av,
                                                const __half* __restrict__ Wb,
                                                float* __restrict__ Cq,
                                                float* __restrict__ Ck,
                                                float* __restrict__ Cv) {
    extern __shared__ __align__(1024) char smem[];
    int t = blockIdx.x;
    const __half *A, *B;
    float* C;
    if (t < 256) { A = Aq; B = Wb; C = Cq; }
    else if (t < 320) { t -= 256; A = Ak; B = Wb + WSTRIDE; C = Ck; }
    else { t -= 320; A = Av; B = Wb + 2 * WSTRIDE; C = Cv; }
    gemm_tile(A, B, C, (t >> 2) * 128, (t & 3) * 128, smem_u32(smem), threadIdx.x);
}

__global__ __launch_bounds__(256) void gemm_one(const __half* __restrict__ A,
                                                const __half* __restrict__ Bt,
                                                float* __restrict__ C) {
    extern __shared__ __align__(1024) char smem[];
    gemm_tile(A, Bt, C, blockIdx.y * 128, blockIdx.x * 128, smem_u32(smem), threadIdx.x);
}

// ---------------------------------------------------------------------------
// fp16 conversions
// ---------------------------------------------------------------------------
struct __align__(8) hf4 { __half a, b, c, d; };

__global__ __launch_bounds__(256) void cvt_act_all(const float4* __restrict__ q,
                                                   const float4* __restrict__ k,
                                                   const float4* __restrict__ v,
                                                   __half* __restrict__ outq,
                                                   __half* __restrict__ outk,
                                                   __half* __restrict__ outv,
                                                   int Mq, int Mkv) {
    const int gid = blockIdx.x * 256 + threadIdx.x;
    const int nq = Mq * 128, nkv = Mkv * 128;
    const float4* src;
    __half* out;
    int loc;
    if (gid < nq) { src = q; out = outq; loc = gid; }
    else if (gid < nq + nkv) { src = k; out = outk; loc = gid - nq; }
    else if (gid < nq + 2 * nkv) { src = v; out = outv; loc = gid - nq - nkv; }
    else return;
    float4 x = src[loc];
    hf4 hv;
    hv.a = __float2half(x.x); hv.b = __float2half(x.y);
    hv.c = __float2half(x.z); hv.d = __float2half(x.w);
    *(hf4*)(out + (size_t)loc * 4) = hv;
}

__global__ void cvt_wT_all(const float* __restrict__ W0, const float* __restrict__ W1,
                           const float* __restrict__ W2, const float* __restrict__ W3,
                           __half* __restrict__ Wb) {
    const float* W = (blockIdx.z == 0) ? W0 : (blockIdx.z == 1) ? W1 : (blockIdx.z == 2) ? W2 : W3;
    __half* outW = Wb + (size_t)blockIdx.z * WSTRIDE;
    __shared__ float t[32][33];
    const int k = blockIdx.y * 32 + threadIdx.y;
    const int n = blockIdx.x * 32 + threadIdx.x;
    t[threadIdx.y][threadIdx.x] = W[k * DMODEL + n];
    __syncthreads();
    const int n2 = blockIdx.x * 32 + threadIdx.y;
    const int k2 = blockIdx.y * 32 + threadIdx.x;
    outW[(size_t)n2 * GK + k2] = __float2half(t[threadIdx.x][threadIdx.y]);
}

// ---------------------------------------------------------------------------
// Sparse attention v3: same per-query math as v2, QBLK=64 for occupancy.
// Grid = 1024 x 16 CTAs (~6.9/SM). Key-window union for 64 queries = 31 cols.
// ---------------------------------------------------------------------------
#define QBLK 64
#define CTILE 32

__device__ __forceinline__ int floordiv_s(int a, int d) {
    return (a >= 0) ? (a / d) : -((-a + d - 1) / d);
}

__global__ __launch_bounds__(256) void sparse_attn_v3(const float* __restrict__ Q,
                                                      const float* __restrict__ Kp,
                                                      const float* __restrict__ Vp,
                                                      __half* __restrict__ ctxh,
                                                      int Lq, int Lkv) {
    __shared__ float4 Ks4[CTILE][17];
    __shared__ float2 Vs2[CTILE][32];

    const int bh = blockIdx.y;
    const int b = bh / HEAD_NUM;
    const int h = bh % HEAD_NUM;
    const int c0 = blockIdx.x * QBLK;
    const int tid = threadIdx.x;
    const int wid = tid >> 5, lane = tid & 31;
    const int rlane = lane & 15;
    const int half = lane >> 4;

    const int colT0 = max(0, c0 / STRIDE - (R_SPAN - 1));

    for (int idx = tid; idx < CTILE * 16; idx += 256) {
        const int col = idx >> 4, d4 = idx & 15;
        if (colT0 + col < Lkv) {
            const size_t off = ((size_t)(b * Lkv + colT0 + col) * DMODEL) + h * 64 + d4 * 4;
            Ks4[col][d4] = __ldg((const float4*)(Kp + off));
        }
    }
    for (int idx = tid; idx < CTILE * 32; idx += 256) {
        const int col = idx >> 5, l2 = idx & 31;
        if (colT0 + col < Lkv) {
            const size_t off = ((size_t)(b * Lkv + colT0 + col) * DMODEL) + h * 64 + l2 * 2;
            Vs2[col][l2] = __ldg((const float2*)(Vp + off));
        }
    }
    __syncthreads();

    // each warp: 8 consecutive queries, 4 steps x 2 (one per half-warp)
    #pragma unroll
    for (int step = 0; step < 4; step++) {
        const int cbase = c0 + wid * 8 + step * 2;
        const int c = cbase + half;

        const int fd = floordiv_s(SPAN - 1 - c, STRIDE);
        const int col = rlane - fd;
        const int row = c - STRIDE * col;
        const bool valid = (row >= 0) && (row < SPAN) && (col >= 0) && (col < Lkv);
        const int ii = min(max(col - colT0, 0), CTILE - 1);

        const float4* Qrow = (const float4*)(Q + ((size_t)(b * Lq + c) * DMODEL) + h * 64);
        float acc = 0.f;
        #pragma unroll
        for (int d4 = 0; d4 < 16; d4++) {
            const float4 qv = __ldg(Qrow + d4);
            const float4 kv = Ks4[ii][d4];
            acc += qv.x * kv.x + qv.y * kv.y + qv.z * kv.z + qv.w * kv.w;
        }
        const float sc = valid ? acc * 0.125f : -1e30f;

        float m = sc;
        #pragma unroll
        for (int off = 8; off > 0; off >>= 1)
            m = fmaxf(m, __shfl_xor_sync(0xffffffffu, m, off));
        const float e = valid ? __expf(sc - m) : 0.f;
        float s = e;
        #pragma unroll
        for (int off = 8; off > 0; off >>= 1)
            s += __shfl_xor_sync(0xffffffffu, s, off);
        const float w = e / s;

        #pragma unroll
        for (int qh = 0; qh < 2; qh++) {
            const int cq = cbase + qh;
            const int fdq = floordiv_s(SPAN - 1 - cq, STRIDE);
            float ox = 0.f, oy = 0.f;
            #pragma unroll
            for (int r = 0; r < R_SPAN; r++) {
                const float wr = __shfl_sync(0xffffffffu, w, qh * 16 + r);
                const int iir = min(max(r - fdq - colT0, 0), CTILE - 1);
                const float2 vv = Vs2[iir][lane];
                ox += wr * vv.x;
                oy += wr * vv.y;
            }
            __half2 hp;
            hp.x = __float2half(ox);
            hp.y = __float2half(oy);
            *(__half2*)(ctxh + (size_t)(b * Lq + cq) * GK + h * DIM_V + 2 * lane) = hp;
        }
    }
}

// ---------------------------------------------------------------------------
// Launch
// ---------------------------------------------------------------------------
extern "C" void kernel_launch(void* const* d_in, const int* in_sizes, int n_in,
                              void* d_out, int out_size) {
    const float* q    = (const float*)d_in[0];
    const float* k    = (const float*)d_in[1];
    const float* v    = (const float*)d_in[2];
    const float* Wq   = (const float*)d_in[3];
    const float* Wk   = (const float*)d_in[4];
    const float* Wv   = (const float*)d_in[5];
    const float* Wout = (const float*)d_in[6];
    float* out = (float*)d_out;

    const int Lq  = in_sizes[0] / (BATCH * DMODEL);   // 4096
    const int Lkv = in_sizes[1] / (BATCH * DMODEL);   // 1024
    const int Mq  = BATCH * Lq;    // 8192
    const int Mkv = BATCH * Lkv;   // 2048

    __half *gAb, *gKb, *gVb, *gWb;
    float *gQ, *gK, *gV;
    cudaGetSymbolAddress((void**)&gAb, g_Ab);
    cudaGetSymbolAddress((void**)&gKb, g_Kb);
    cudaGetSymbolAddress((void**)&gVb, g_Vb);
    cudaGetSymbolAddress((void**)&gWb, g_Wb4);
    cudaGetSymbolAddress((void**)&gQ, g_Q);
    cudaGetSymbolAddress((void**)&gK, g_K);
    cudaGetSymbolAddress((void**)&gV, g_V);

    cudaFuncSetAttribute(gemm_qkv, cudaFuncAttributeMaxDynamicSharedMemorySize, GEMM_SMEM);
    cudaFuncSetAttribute(gemm_one, cudaFuncAttributeMaxDynamicSharedMemorySize, GEMM_SMEM);

    cvt_wT_all<<<dim3(16, 16, 4), dim3(32, 32)>>>(Wq, Wk, Wv, Wout, gWb);

    const int tot = (Mq + 2 * Mkv) * 128;
    cvt_act_all<<<(tot + 255) / 256, 256>>>((const float4*)q, (const float4*)k,
                                            (const float4*)v, gAb, gKb, gVb, Mq, Mkv);

    gemm_qkv<<<384, 256, GEMM_SMEM>>>(gAb, gKb, gVb, gWb, gQ, gK, gV);

    sparse_attn_v3<<<dim3(Lq / QBLK, BATCH * HEAD_NUM), 256>>>(gQ, gK, gV, gAb, Lq, Lkv);

    gemm_one<<<dim3(4, Mq / 128), 256, GEMM_SMEM>>>(gAb, gWb + 3 * (size_t)WSTRIDE, out);
}

// round 11
// speedup vs baseline: 6.0727x; 1.0417x over previous
#include <cuda_runtime.h>
#include <cuda_fp16.h>
#include <cstdint>

#define HEAD_NUM 8
#define DIM_QK 64
#define DIM_V 64
#define SPAN 64
#define STRIDE 4
#define R_SPAN 16

#define BATCH 2
#define MAX_LQ 4096
#define MAX_LKV 1024
#define DMODEL 512
#define GK 512           // single-rounded fp16 GEMM
#define CHUNKS 8         // GK / 64
#define WSTRIDE (DMODEL * GK)

// ---------------------------------------------------------------------------
// Scratch (no cudaMalloc allowed)
// ---------------------------------------------------------------------------
__device__ __align__(16) __half g_Ab[BATCH * MAX_LQ * GK];    // q fp16, then ctx fp16
__device__ __align__(16) __half g_Kb[BATCH * MAX_LKV * GK];   // k fp16
__device__ __align__(16) __half g_Vb[BATCH * MAX_LKV * GK];   // v fp16
__device__ __align__(16) __half g_Wb4[4 * WSTRIDE];           // 4 weights (transposed) fp16
__device__ __align__(16) float g_Q[BATCH * MAX_LQ * DMODEL];
__device__ __align__(16) float g_K[BATCH * MAX_LKV * DMODEL];
__device__ __align__(16) float g_V[BATCH * MAX_LKV * DMODEL];

// ---------------------------------------------------------------------------
// Baseline-target PTX helpers
// ---------------------------------------------------------------------------
__device__ __forceinline__ uint32_t smem_u32(const void* p) {
    uint32_t a;
    asm("{ .reg .u64 t; cvta.to.shared.u64 t, %1; cvt.u32.u64 %0, t; }" : "=r"(a) : "l"(p));
    return a;
}
__device__ __forceinline__ void cp_async16(uint32_t saddr, const void* gaddr) {
    asm volatile("cp.async.cg.shared.global [%0], [%1], 16;" :: "r"(saddr), "l"(gaddr));
}
__device__ __forceinline__ void cp_commit() { asm volatile("cp.async.commit_group;" ::: "memory"); }
__device__ __forceinline__ void cp_wait1() { asm volatile("cp.async.wait_group 1;" ::: "memory"); }
__device__ __forceinline__ void cp_wait0() { asm volatile("cp.async.wait_group 0;" ::: "memory"); }
__device__ __forceinline__ void ldm_x4(uint32_t* r, uint32_t addr) {
    asm volatile("ldmatrix.sync.aligned.m8n8.x4.shared.b16 {%0,%1,%2,%3}, [%4];"
                 : "=r"(r[0]), "=r"(r[1]), "=r"(r[2]), "=r"(r[3]) : "r"(addr));
}
__device__ __forceinline__ void ldm_x2(uint32_t* r, uint32_t addr) {
    asm volatile("ldmatrix.sync.aligned.m8n8.x2.shared.b16 {%0,%1}, [%2];"
                 : "=r"(r[0]), "=r"(r[1]) : "r"(addr));
}
__device__ __forceinline__ void mma_f16(float* c, const uint32_t* a, const uint32_t* b) {
    asm volatile("mma.sync.aligned.m16n8k16.row.col.f32.f16.f16.f32 "
                 "{%0,%1,%2,%3}, {%4,%5,%6,%7}, {%8,%9}, {%0,%1,%2,%3};"
                 : "+f"(c[0]), "+f"(c[1]), "+f"(c[2]), "+f"(c[3])
                 : "r"(a[0]), "r"(a[1]), "r"(a[2]), "r"(a[3]), "r"(b[0]), "r"(b[1]));
}
__device__ __forceinline__ uint32_t sw128(uint32_t off) { return off ^ ((off >> 3) & 0x70); }

// ---------------------------------------------------------------------------
// GEMM tile worker (unchanged from R9/R10): 3-stage cp.async pipeline.
// ---------------------------------------------------------------------------
#define STAGE_BYTES 32768u
#define GEMM_SMEM (3 * STAGE_BYTES)

__device__ __forceinline__ void issue_chunk(const __half* __restrict__ A,
                                            const __half* __restrict__ Bt,
                                            uint32_t sb, int row0, int col0,
                                            int chunk, int stage, int tid) {
    const int k0 = chunk * 64;
    const uint32_t aoff = stage * STAGE_BYTES;
    const uint32_t boff = aoff + 16384u;
    #pragma unroll
    for (int p = 0; p < 4; p++) {
        const int idx = tid + p * 256;
        const int r = idx >> 3;
        const int c8 = idx & 7;
        const uint32_t sw = sw128((uint32_t)(r * 128 + c8 * 16));
        cp_async16(sb + aoff + sw, A + (size_t)(row0 + r) * GK + k0 + c8 * 8);
        cp_async16(sb + boff + sw, Bt + (size_t)(col0 + r) * GK + k0 + c8 * 8);
    }
    cp_commit();
}

__device__ __forceinline__ void gemm_tile(const __half* __restrict__ A,
                                          const __half* __restrict__ Bt,
                                          float* __restrict__ C,
                                          int row0, int col0, uint32_t sb, int tid) {
    const int wid = tid >> 5, lane = tid & 31;
    const int warpM = wid >> 2, warpN = wid & 3;

    float acc[4][4][4];
    #pragma unroll
    for (int mi = 0; mi < 4; mi++)
        #pragma unroll
        for (int ni = 0; ni < 4; ni++)
            #pragma unroll
            for (int j = 0; j < 4; j++) acc[mi][ni][j] = 0.f;

    const int a_row_in_warp = lane & 15;
    const int a_khalf = (lane >> 4) & 1;
    const int b_row_in_tile = lane & 7;
    const int b_khalf = (lane >> 3) & 1;

    issue_chunk(A, Bt, sb, row0, col0, 0, 0, tid);
    issue_chunk(A, Bt, sb, row0, col0, 1, 1, tid);

    int stage = 0, nstage = 2;
    for (int i = 0; i < CHUNKS; i++) {
        if (i + 1 < CHUNKS) cp_wait1(); else cp_wait0();
        __syncthreads();

        if (i + 2 < CHUNKS) {
            issue_chunk(A, Bt, sb, row0, col0, i + 2, nstage, tid);
            nstage = (nstage + 1 == 3) ? 0 : nstage + 1;
        }

        const uint32_t aoff = stage * STAGE_BYTES;
        const uint32_t boff = aoff + 16384u;
        #pragma unroll
        for (int kk = 0; kk < 4; kk++) {
            uint32_t afrag[4][4], bfrag[4][2];
            #pragma unroll
            for (int mi = 0; mi < 4; mi++) {
                const int r = warpM * 64 + mi * 16 + a_row_in_warp;
                ldm_x4(afrag[mi], sb + aoff + sw128((uint32_t)(r * 128 + kk * 32 + a_khalf * 16)));
            }
            #pragma unroll
            for (int ni = 0; ni < 4; ni++) {
                const int r = warpN * 32 + ni * 8 + b_row_in_tile;
                ldm_x2(bfrag[ni], sb + boff + sw128((uint32_t)(r * 128 + kk * 32 + b_khalf * 16)));
            }
            #pragma unroll
            for (int mi = 0; mi < 4; mi++)
                #pragma unroll
                for (int ni = 0; ni < 4; ni++)
                    mma_f16(acc[mi][ni], afrag[mi], bfrag[ni]);
        }
        stage = (stage + 1 == 3) ? 0 : stage + 1;
    }

    const int erow = lane >> 2;
    const int ecol = 2 * (lane & 3);
    #pragma unroll
    for (int mi = 0; mi < 4; mi++) {
        #pragma unroll
        for (int ni = 0; ni < 4; ni++) {
            const int r = row0 + warpM * 64 + mi * 16 + erow;
            const int c = col0 + warpN * 32 + ni * 8 + ecol;
            *(float2*)(C + (size_t)r * DMODEL + c) = make_float2(acc[mi][ni][0], acc[mi][ni][1]);
            *(float2*)(C + (size_t)(r + 8) * DMODEL + c) = make_float2(acc[mi][ni][2], acc[mi][ni][3]);
        }
    }
}

__global__ __launch_bounds__(256) void gemm_qkv(const __half* __restrict__ Aq,
                                                const __half* __restrict__ Ak,
                                                const __half* __restrict__ Av,
                                                const __half* __restrict__ Wb,
                                                float* __restrict__ Cq,
                                                float* __restrict__ Ck,
                                                float* __restrict__ Cv) {
    extern __shared__ __align__(1024) char smem[];
    int t = blockIdx.x;
    const __half *A, *B;
    float* C;
    if (t < 256) { A = Aq; B = Wb; C = Cq; }
    else if (t < 320) { t -= 256; A = Ak; B = Wb + WSTRIDE; C = Ck; }
    else { t -= 320; A = Av; B = Wb + 2 * WSTRIDE; C = Cv; }
    gemm_tile(A, B, C, (t >> 2) * 128, (t & 3) * 128, smem_u32(smem), threadIdx.x);
}

__global__ __launch_bounds__(256) void gemm_one(const __half* __restrict__ A,
                                                const __half* __restrict__ Bt,
                                                float* __restrict__ C) {
    extern __shared__ __align__(1024) char smem[];
    gemm_tile(A, Bt, C, blockIdx.y * 128, blockIdx.x * 128, smem_u32(smem), threadIdx.x);
}

// ---------------------------------------------------------------------------
// fp16 conversions
// ---------------------------------------------------------------------------
struct __align__(8) hf4 { __half a, b, c, d; };

__global__ __launch_bounds__(256) void cvt_act_all(const float4* __restrict__ q,
                                                   const float4* __restrict__ k,
                                                   const float4* __restrict__ v,
                                                   __half* __restrict__ outq,
                                                   __half* __restrict__ outk,
                                                   __half* __restrict__ outv,
                                                   int Mq, int Mkv) {
    const int gid = blockIdx.x * 256 + threadIdx.x;
    const int nq = Mq * 128, nkv = Mkv * 128;
    const float4* src;
    __half* out;
    int loc;
    if (gid < nq) { src = q; out = outq; loc = gid; }
    else if (gid < nq + nkv) { src = k; out = outk; loc = gid - nq; }
    else if (gid < nq + 2 * nkv) { src = v; out = outv; loc = gid - nq - nkv; }
    else return;
    float4 x = src[loc];
    hf4 hv;
    hv.a = __float2half(x.x); hv.b = __float2half(x.y);
    hv.c = __float2half(x.z); hv.d = __float2half(x.w);
    *(hf4*)(out + (size_t)loc * 4) = hv;
}

__global__ void cvt_wT_all(const float* __restrict__ W0, const float* __restrict__ W1,
                           const float* __restrict__ W2, const float* __restrict__ W3,
                           __half* __restrict__ Wb) {
    const float* W = (blockIdx.z == 0) ? W0 : (blockIdx.z == 1) ? W1 : (blockIdx.z == 2) ? W2 : W3;
    __half* outW = Wb + (size_t)blockIdx.z * WSTRIDE;
    __shared__ float t[32][33];
    const int k = blockIdx.y * 32 + threadIdx.y;
    const int n = blockIdx.x * 32 + threadIdx.x;
    t[threadIdx.y][threadIdx.x] = W[k * DMODEL + n];
    __syncthreads();
    const int n2 = blockIdx.x * 32 + threadIdx.y;
    const int k2 = blockIdx.y * 32 + threadIdx.x;
    outW[(size_t)n2 * GK + k2] = __float2half(t[threadIdx.x][threadIdx.y]);
}

// ---------------------------------------------------------------------------
// Sparse attention v4: fp16 K/V smem tiles (half the LDS wavefronts).
// K row stride = 36 half2 (144B = 9*16B): 16B-aligned, quarter-warp
// granule-bank (ii + j8) mod 8 conflict-free. Q stays fp32 (error control).
// ---------------------------------------------------------------------------
#define QBLK 64
#define CTILE 32
#define KSTRIDE 36   // half2 elements per K row (32 data + 4 pad)

__device__ __forceinline__ int floordiv_s(int a, int d) {
    return (a >= 0) ? (a / d) : -((-a + d - 1) / d);
}

__global__ __launch_bounds__(256) void sparse_attn_v4(const float* __restrict__ Q,
                                                      const float* __restrict__ Kp,
                                                      const float* __restrict__ Vp,
                                                      __half* __restrict__ ctxh,
                                                      int Lq, int Lkv) {
    __shared__ __align__(16) __half2 Ksh[CTILE][KSTRIDE];  // [col][dim-pair]
    __shared__ __half2 Vsh[CTILE][32];                     // [col][lane] dims (2l,2l+1)

    const int bh = blockIdx.y;
    const int b = bh / HEAD_NUM;
    const int h = bh % HEAD_NUM;
    const int c0 = blockIdx.x * QBLK;
    const int tid = threadIdx.x;
    const int wid = tid >> 5, lane = tid & 31;
    const int rlane = lane & 15;
    const int half = lane >> 4;

    const int colT0 = max(0, c0 / STRIDE - (R_SPAN - 1));

    // K tile: convert fp32 -> half2 on load
    for (int idx = tid; idx < CTILE * 16; idx += 256) {
        const int col = idx >> 4, d4 = idx & 15;
        if (colT0 + col < Lkv) {
            const size_t off = ((size_t)(b * Lkv + colT0 + col) * DMODEL) + h * 64 + d4 * 4;
            const float4 kv = __ldg((const float4*)(Kp + off));
            Ksh[col][2 * d4]     = __floats2half2_rn(kv.x, kv.y);
            Ksh[col][2 * d4 + 1] = __floats2half2_rn(kv.z, kv.w);
        }
    }
    // V tile: convert fp32 -> half2 on load
    for (int idx = tid; idx < CTILE * 32; idx += 256) {
        const int col = idx >> 5, l2 = idx & 31;
        if (colT0 + col < Lkv) {
            const size_t off = ((size_t)(b * Lkv + colT0 + col) * DMODEL) + h * 64 + l2 * 2;
            const float2 vv = __ldg((const float2*)(Vp + off));
            Vsh[col][l2] = __floats2half2_rn(vv.x, vv.y);
        }
    }
    __syncthreads();

    // each warp: 8 consecutive queries, 4 steps x 2 (one per half-warp)
    #pragma unroll
    for (int step = 0; step < 4; step++) {
        const int cbase = c0 + wid * 8 + step * 2;
        const int c = cbase + half;

        const int fd = floordiv_s(SPAN - 1 - c, STRIDE);
        const int col = rlane - fd;
        const int row = c - STRIDE * col;
        const bool valid = (row >= 0) && (row < SPAN) && (col >= 0) && (col < Lkv);
        const int ii = min(max(col - colT0, 0), CTILE - 1);

        // 64-dim dot: 8 x (LDS.128 of 4 half2 + 2 LDG.128 Q + 8 FMA)
        const float4* Qrow = (const float4*)(Q + ((size_t)(b * Lq + c) * DMODEL) + h * 64);
        float acc = 0.f;
        #pragma unroll
        for (int j8 = 0; j8 < 8; j8++) {
            const uint4 kp = *(const uint4*)&Ksh[ii][j8 * 4];
            const float4 qa = __ldg(Qrow + 2 * j8);
            const float4 qb = __ldg(Qrow + 2 * j8 + 1);
            const float2 k0 = __half22float2(*(const __half2*)&kp.x);
            const float2 k1 = __half22float2(*(const __half2*)&kp.y);
            const float2 k2 = __half22float2(*(const __half2*)&kp.z);
            const float2 k3 = __half22float2(*(const __half2*)&kp.w);
            acc += qa.x * k0.x + qa.y * k0.y + qa.z * k1.x + qa.w * k1.y;
            acc += qb.x * k2.x + qb.y * k2.y + qb.z * k3.x + qb.w * k3.y;
        }
        const float sc = valid ? acc * 0.125f : -1e30f;

        // softmax over the 16 lanes of this half-warp
        float m = sc;
        #pragma unroll
        for (int off = 8; off > 0; off >>= 1)
            m = fmaxf(m, __shfl_xor_sync(0xffffffffu, m, off));
        const float e = valid ? __expf(sc - m) : 0.f;
        float s = e;
        #pragma unroll
        for (int off = 8; off > 0; off >>= 1)
            s += __shfl_xor_sync(0xffffffffu, s, off);
        const float w = e / s;

        // V accumulation: per-lane dims (2l, 2l+1), LDS.32 per key
        #pragma unroll
        for (int qh = 0; qh < 2; qh++) {
            const int cq = cbase + qh;
            const int fdq = floordiv_s(SPAN - 1 - cq, STRIDE);
            float ox = 0.f, oy = 0.f;
            #pragma unroll
            for (int r = 0; r < R_SPAN; r++) {
                const float wr = __shfl_sync(0xffffffffu, w, qh * 16 + r);
                const int iir = min(max(r - fdq - colT0, 0), CTILE - 1);
                const float2 vv = __half22float2(Vsh[iir][lane]);
                ox += wr * vv.x;
                oy += wr * vv.y;
            }
            __half2 hp;
            hp.x = __float2half(ox);
            hp.y = __float2half(oy);
            *(__half2*)(ctxh + (size_t)(b * Lq + cq) * GK + h * DIM_V + 2 * lane) = hp;
        }
    }
}

// ---------------------------------------------------------------------------
// Launch
// ---------------------------------------------------------------------------
extern "C" void kernel_launch(void* const* d_in, const int* in_sizes, int n_in,
                              void* d_out, int out_size) {
    const float* q    = (const float*)d_in[0];
    const float* k    = (const float*)d_in[1];
    const float* v    = (const float*)d_in[2];
    const float* Wq   = (const float*)d_in[3];
    const float* Wk   = (const float*)d_in[4];
    const float* Wv   = (const float*)d_in[5];
    const float* Wout = (const float*)d_in[6];
    float* out = (float*)d_out;

    const int Lq  = in_sizes[0] / (BATCH * DMODEL);   // 4096
    const int Lkv = in_sizes[1] / (BATCH * DMODEL);   // 1024
    const int Mq  = BATCH * Lq;    // 8192
    const int Mkv = BATCH * Lkv;   // 2048

    __half *gAb, *gKb, *gVb, *gWb;
    float *gQ, *gK, *gV;
    cudaGetSymbolAddress((void**)&gAb, g_Ab);
    cudaGetSymbolAddress((void**)&gKb, g_Kb);
    cudaGetSymbolAddress((void**)&gVb, g_Vb);
    cudaGetSymbolAddress((void**)&gWb, g_Wb4);
    cudaGetSymbolAddress((void**)&gQ, g_Q);
    cudaGetSymbolAddress((void**)&gK, g_K);
    cudaGetSymbolAddress((void**)&gV, g_V);

    cudaFuncSetAttribute(gemm_qkv, cudaFuncAttributeMaxDynamicSharedMemorySize, GEMM_SMEM);
    cudaFuncSetAttribute(gemm_one, cudaFuncAttributeMaxDynamicSharedMemorySize, GEMM_SMEM);

    cvt_wT_all<<<dim3(16, 16, 4), dim3(32, 32)>>>(Wq, Wk, Wv, Wout, gWb);

    const int tot = (Mq + 2 * Mkv) * 128;
    cvt_act_all<<<(tot + 255) / 256, 256>>>((const float4*)q, (const float4*)k,
                                            (const float4*)v, gAb, gKb, gVb, Mq, Mkv);

    gemm_qkv<<<384, 256, GEMM_SMEM>>>(gAb, gKb, gVb, gWb, gQ, gK, gV);

    sparse_attn_v4<<<dim3(Lq / QBLK, BATCH * HEAD_NUM), 256>>>(gQ, gK, gV, gAb, Lq, Lkv);

    gemm_one<<<dim3(4, Mq / 128), 256, GEMM_SMEM>>>(gAb, gWb + 3 * (size_t)WSTRIDE, out);
}

// round 12
// speedup vs baseline: 7.0961x; 1.1685x over previous
#include <cuda_runtime.h>
#include <cuda_fp16.h>
#include <cstdint>

#define HEAD_NUM 8
#define DIM_QK 64
#define DIM_V 64
#define SPAN 64
#define STRIDE 4
#define R_SPAN 16

#define BATCH 2
#define MAX_LQ 4096
#define MAX_LKV 1024
#define DMODEL 512
#define GK 512           // single-rounded fp16 GEMM
#define CHUNKS 8         // GK / 64
#define WSTRIDE (DMODEL * GK)

// ---------------------------------------------------------------------------
// Scratch (no cudaMalloc allowed)
// ---------------------------------------------------------------------------
__device__ __align__(16) __half g_Ab[BATCH * MAX_LQ * GK];    // q-act fp16, then ctx fp16
__device__ __align__(16) __half g_Kb[BATCH * MAX_LKV * GK];   // k-act fp16
__device__ __align__(16) __half g_Vb[BATCH * MAX_LKV * GK];   // v-act fp16
__device__ __align__(16) __half g_Wb4[4 * WSTRIDE];           // 4 weights (transposed) fp16
__device__ __align__(16) __half g_Qh[BATCH * MAX_LQ * DMODEL];   // projected Q (fp16)
__device__ __align__(16) __half g_Kh[BATCH * MAX_LKV * DMODEL];  // projected K (fp16)
__device__ __align__(16) __half g_Vh[BATCH * MAX_LKV * DMODEL];  // projected V (fp16)

// ---------------------------------------------------------------------------
// Baseline-target PTX helpers
// ---------------------------------------------------------------------------
__device__ __forceinline__ uint32_t smem_u32(const void* p) {
    uint32_t a;
    asm("{ .reg .u64 t; cvta.to.shared.u64 t, %1; cvt.u32.u64 %0, t; }" : "=r"(a) : "l"(p));
    return a;
}
__device__ __forceinline__ void cp_async16(uint32_t saddr, const void* gaddr) {
    asm volatile("cp.async.cg.shared.global [%0], [%1], 16;" :: "r"(saddr), "l"(gaddr));
}
__device__ __forceinline__ void cp_commit() { asm volatile("cp.async.commit_group;" ::: "memory"); }
__device__ __forceinline__ void cp_wait1() { asm volatile("cp.async.wait_group 1;" ::: "memory"); }
__device__ __forceinline__ void cp_wait0() { asm volatile("cp.async.wait_group 0;" ::: "memory"); }
__device__ __forceinline__ void ldm_x4(uint32_t* r, uint32_t addr) {
    asm volatile("ldmatrix.sync.aligned.m8n8.x4.shared.b16 {%0,%1,%2,%3}, [%4];"
                 : "=r"(r[0]), "=r"(r[1]), "=r"(r[2]), "=r"(r[3]) : "r"(addr));
}
__device__ __forceinline__ void ldm_x2(uint32_t* r, uint32_t addr) {
    asm volatile("ldmatrix.sync.aligned.m8n8.x2.shared.b16 {%0,%1}, [%2];"
                 : "=r"(r[0]), "=r"(r[1]) : "r"(addr));
}
__device__ __forceinline__ void mma_f16(float* c, const uint32_t* a, const uint32_t* b) {
    asm volatile("mma.sync.aligned.m16n8k16.row.col.f32.f16.f16.f32 "
                 "{%0,%1,%2,%3}, {%4,%5,%6,%7}, {%8,%9}, {%0,%1,%2,%3};"
                 : "+f"(c[0]), "+f"(c[1]), "+f"(c[2]), "+f"(c[3])
                 : "r"(a[0]), "r"(a[1]), "r"(a[2]), "r"(a[3]), "r"(b[0]), "r"(b[1]));
}
__device__ __forceinline__ uint32_t sw128(uint32_t off) { return off ^ ((off >> 3) & 0x70); }

// ---------------------------------------------------------------------------
// GEMM tile worker, templated on output type (fp16 for Q/K/V, fp32 for out).
// 3-stage cp.async pipeline, one __syncthreads per K-chunk.
// ---------------------------------------------------------------------------
#define STAGE_BYTES 32768u
#define GEMM_SMEM (3 * STAGE_BYTES)

__device__ __forceinline__ void issue_chunk(const __half* __restrict__ A,
                                            const __half* __restrict__ Bt,
                                            uint32_t sb, int row0, int col0,
                                            int chunk, int stage, int tid) {
    const int k0 = chunk * 64;
    const uint32_t aoff = stage * STAGE_BYTES;
    const uint32_t boff = aoff + 16384u;
    #pragma unroll
    for (int p = 0; p < 4; p++) {
        const int idx = tid + p * 256;
        const int r = idx >> 3;
        const int c8 = idx & 7;
        const uint32_t sw = sw128((uint32_t)(r * 128 + c8 * 16));
        cp_async16(sb + aoff + sw, A + (size_t)(row0 + r) * GK + k0 + c8 * 8);
        cp_async16(sb + boff + sw, Bt + (size_t)(col0 + r) * GK + k0 + c8 * 8);
    }
    cp_commit();
}

template <bool HOUT>
__device__ __forceinline__ void gemm_tile(const __half* __restrict__ A,
                                          const __half* __restrict__ Bt,
                                          void* __restrict__ Cp,
                                          int row0, int col0, uint32_t sb, int tid) {
    const int wid = tid >> 5, lane = tid & 31;
    const int warpM = wid >> 2, warpN = wid & 3;

    float acc[4][4][4];
    #pragma unroll
    for (int mi = 0; mi < 4; mi++)
        #pragma unroll
        for (int ni = 0; ni < 4; ni++)
            #pragma unroll
            for (int j = 0; j < 4; j++) acc[mi][ni][j] = 0.f;

    const int a_row_in_warp = lane & 15;
    const int a_khalf = (lane >> 4) & 1;
    const int b_row_in_tile = lane & 7;
    const int b_khalf = (lane >> 3) & 1;

    issue_chunk(A, Bt, sb, row0, col0, 0, 0, tid);
    issue_chunk(A, Bt, sb, row0, col0, 1, 1, tid);

    int stage = 0, nstage = 2;
    for (int i = 0; i < CHUNKS; i++) {
        if (i + 1 < CHUNKS) cp_wait1(); else cp_wait0();
        __syncthreads();

        if (i + 2 < CHUNKS) {
            issue_chunk(A, Bt, sb, row0, col0, i + 2, nstage, tid);
            nstage = (nstage + 1 == 3) ? 0 : nstage + 1;
        }

        const uint32_t aoff = stage * STAGE_BYTES;
        const uint32_t boff = aoff + 16384u;
        #pragma unroll
        for (int kk = 0; kk < 4; kk++) {
            uint32_t afrag[4][4], bfrag[4][2];
            #pragma unroll
            for (int mi = 0; mi < 4; mi++) {
                const int r = warpM * 64 + mi * 16 + a_row_in_warp;
                ldm_x4(afrag[mi], sb + aoff + sw128((uint32_t)(r * 128 + kk * 32 + a_khalf * 16)));
            }
            #pragma unroll
            for (int ni = 0; ni < 4; ni++) {
                const int r = warpN * 32 + ni * 8 + b_row_in_tile;
                ldm_x2(bfrag[ni], sb + boff + sw128((uint32_t)(r * 128 + kk * 32 + b_khalf * 16)));
            }
            #pragma unroll
            for (int mi = 0; mi < 4; mi++)
                #pragma unroll
                for (int ni = 0; ni < 4; ni++)
                    mma_f16(acc[mi][ni], afrag[mi], bfrag[ni]);
        }
        stage = (stage + 1 == 3) ? 0 : stage + 1;
    }

    const int erow = lane >> 2;
    const int ecol = 2 * (lane & 3);
    #pragma unroll
    for (int mi = 0; mi < 4; mi++) {
        #pragma unroll
        for (int ni = 0; ni < 4; ni++) {
            const int r = row0 + warpM * 64 + mi * 16 + erow;
            const int c = col0 + warpN * 32 + ni * 8 + ecol;
            if (HOUT) {
                __half* C = (__half*)Cp;
                *(__half2*)(C + (size_t)r * DMODEL + c) =
                    __floats2half2_rn(acc[mi][ni][0], acc[mi][ni][1]);
                *(__half2*)(C + (size_t)(r + 8) * DMODEL + c) =
                    __floats2half2_rn(acc[mi][ni][2], acc[mi][ni][3]);
            } else {
                float* C = (float*)Cp;
                *(float2*)(C + (size_t)r * DMODEL + c) = make_float2(acc[mi][ni][0], acc[mi][ni][1]);
                *(float2*)(C + (size_t)(r + 8) * DMODEL + c) = make_float2(acc[mi][ni][2], acc[mi][ni][3]);
            }
        }
    }
}

__global__ __launch_bounds__(256) void gemm_qkv(const __half* __restrict__ Aq,
                                                const __half* __restrict__ Ak,
                                                const __half* __restrict__ Av,
                                                const __half* __restrict__ Wb,
                                                __half* __restrict__ Cq,
                                                __half* __restrict__ Ck,
                                                __half* __restrict__ Cv) {
    extern __shared__ __align__(1024) char smem[];
    int t = blockIdx.x;
    const __half *A, *B;
    __half* C;
    if (t < 256) { A = Aq; B = Wb; C = Cq; }
    else if (t < 320) { t -= 256; A = Ak; B = Wb + WSTRIDE; C = Ck; }
    else { t -= 320; A = Av; B = Wb + 2 * WSTRIDE; C = Cv; }
    gemm_tile<true>(A, B, C, (t >> 2) * 128, (t & 3) * 128, smem_u32(smem), threadIdx.x);
}

__global__ __launch_bounds__(256) void gemm_one(const __half* __restrict__ A,
                                                const __half* __restrict__ Bt,
                                                float* __restrict__ C) {
    extern __shared__ __align__(1024) char smem[];
    gemm_tile<false>(A, Bt, C, blockIdx.y * 128, blockIdx.x * 128, smem_u32(smem), threadIdx.x);
}

// ---------------------------------------------------------------------------
// prep_all: fused activation fp16 conversion + weight transpose/convert.
// Blocks [0, nact) convert activations; blocks [nact, nact+1024) do weights.
// ---------------------------------------------------------------------------
struct __align__(8) hf4 { __half a, b, c, d; };

__global__ __launch_bounds__(256) void prep_all(const float4* __restrict__ q,
                                                const float4* __restrict__ k,
                                                const float4* __restrict__ v,
                                                const float* __restrict__ W0,
                                                const float* __restrict__ W1,
                                                const float* __restrict__ W2,
                                                const float* __restrict__ W3,
                                                __half* __restrict__ outq,
                                                __half* __restrict__ outk,
                                                __half* __restrict__ outv,
                                                __half* __restrict__ Wb,
                                                int Mq, int Mkv) {
    __shared__ float tbuf[32][33];
    const int nq = Mq * 128, nkv = Mkv * 128;
    const int nact = (nq + 2 * nkv + 255) / 256;
    const int tid = threadIdx.x;

    if ((int)blockIdx.x < nact) {
        const int gid = blockIdx.x * 256 + tid;
        const float4* src;
        __half* out;
        int loc;
        if (gid < nq) { src = q; out = outq; loc = gid; }
        else if (gid < nq + nkv) { src = k; out = outk; loc = gid - nq; }
        else if (gid < nq + 2 * nkv) { src = v; out = outv; loc = gid - nq - nkv; }
        else return;
        float4 x = src[loc];
        hf4 hv;
        hv.a = __float2half(x.x); hv.b = __float2half(x.y);
        hv.c = __float2half(x.z); hv.d = __float2half(x.w);
        *(hf4*)(out + (size_t)loc * 4) = hv;
    } else {
        int t = blockIdx.x - nact;          // 0..1023
        const int z = t >> 8;               // weight 0..3
        const int tt = t & 255;             // tile 0..255
        const int k0 = (tt >> 4) * 32, n0 = (tt & 15) * 32;
        const float* W = (z == 0) ? W0 : (z == 1) ? W1 : (z == 2) ? W2 : W3;
        __half* outW = Wb + (size_t)z * WSTRIDE;
        const int r0 = tid >> 5, cc = tid & 31;
        #pragma unroll
        for (int j = 0; j < 4; j++)
            tbuf[r0 + j * 8][cc] = W[(size_t)(k0 + r0 + j * 8) * DMODEL + n0 + cc];
        __syncthreads();
        #pragma unroll
        for (int j = 0; j < 4; j++)
            outW[(size_t)(n0 + r0 + j * 8) * GK + k0 + cc] = __float2half(tbuf[cc][r0 + j * 8]);
    }
}

// ---------------------------------------------------------------------------
// Sparse attention v5: all-fp16 inputs (Q/K/V projected fp16), fp16 tiles.
// ---------------------------------------------------------------------------
#define QBLK 64
#define CTILE 32
#define KSTRIDE 36   // half2 per K row (32 data + 4 pad), 144B = 9x16B

__device__ __forceinline__ int floordiv_s(int a, int d) {
    return (a >= 0) ? (a / d) : -((-a + d - 1) / d);
}

__global__ __launch_bounds__(256) void sparse_attn_v5(const __half* __restrict__ Qh,
                                                      const __half* __restrict__ Kh,
                                                      const __half* __restrict__ Vh,
                                                      __half* __restrict__ ctxh,
                                                      int Lq, int Lkv) {
    __shared__ __align__(16) __half2 Ksh[CTILE][KSTRIDE];
    __shared__ __align__(16) __half2 Vsh[CTILE][32];

    const int bh = blockIdx.y;
    const int b = bh / HEAD_NUM;
    const int h = bh % HEAD_NUM;
    const int c0 = blockIdx.x * QBLK;
    const int tid = threadIdx.x;
    const int wid = tid >> 5, lane = tid & 31;
    const int rlane = lane & 15;
    const int half = lane >> 4;

    const int colT0 = max(0, c0 / STRIDE - (R_SPAN - 1));

    // K tile: 32 cols x 8 x 16B, direct fp16 copy (256 threads, 1 iter)
    {
        const int col = tid >> 3, d8 = tid & 7;
        if (colT0 + col < Lkv) {
            const uint4 kv = __ldg((const uint4*)(Kh + ((size_t)(b * Lkv + colT0 + col) * DMODEL) + h * 64 + d8 * 8));
            *(uint4*)&Ksh[col][d8 * 4] = kv;
        }
    }
    // V tile: 32 cols x 8 x 16B
    {
        const int col = tid >> 3, l8 = tid & 7;
        if (colT0 + col < Lkv) {
            const uint4 vv = __ldg((const uint4*)(Vh + ((size_t)(b * Lkv + colT0 + col) * DMODEL) + h * 64 + l8 * 8));
            *(uint4*)&Vsh[col][l8 * 4] = vv;
        }
    }
    __syncthreads();

    // each warp: 8 consecutive queries, 4 steps x 2 (one per half-warp)
    #pragma unroll
    for (int step = 0; step < 4; step++) {
        const int cbase = c0 + wid * 8 + step * 2;
        const int c = cbase + half;

        const int fd = floordiv_s(SPAN - 1 - c, STRIDE);
        const int col = rlane - fd;
        const int row = c - STRIDE * col;
        const bool valid = (row >= 0) && (row < SPAN) && (col >= 0) && (col < Lkv);
        const int ii = min(max(col - colT0, 0), CTILE - 1);

        // 64-dim dot, fp32 accumulation from fp16 operands
        const uint4* Qrow = (const uint4*)(Qh + ((size_t)(b * Lq + c) * DMODEL) + h * 64);
        float acc = 0.f;
        #pragma unroll
        for (int j8 = 0; j8 < 8; j8++) {
            const uint4 qp = __ldg(Qrow + j8);
            const uint4 kp = *(const uint4*)&Ksh[ii][j8 * 4];
            const float2 q0 = __half22float2(*(const __half2*)&qp.x);
            const float2 q1 = __half22float2(*(const __half2*)&qp.y);
            const float2 q2 = __half22float2(*(const __half2*)&qp.z);
            const float2 q3 = __half22float2(*(const __half2*)&qp.w);
            const float2 k0 = __half22float2(*(const __half2*)&kp.x);
            const float2 k1 = __half22float2(*(const __half2*)&kp.y);
            const float2 k2 = __half22float2(*(const __half2*)&kp.z);
            const float2 k3 = __half22float2(*(const __half2*)&kp.w);
            acc += q0.x * k0.x + q0.y * k0.y + q1.x * k1.x + q1.y * k1.y;
            acc += q2.x * k2.x + q2.y * k2.y + q3.x * k3.x + q3.y * k3.y;
        }
        const float sc = valid ? acc * 0.125f : -1e30f;

        float m = sc;
        #pragma unroll
        for (int off = 8; off > 0; off >>= 1)
            m = fmaxf(m, __shfl_xor_sync(0xffffffffu, m, off));
        const float e = valid ? __expf(sc - m) : 0.f;
        float s = e;
        #pragma unroll
        for (int off = 8; off > 0; off >>= 1)
            s += __shfl_xor_sync(0xffffffffu, s, off);
        const float w = e / s;

        #pragma unroll
        for (int qh = 0; qh < 2; qh++) {
            const int cq = cbase + qh;
            const int fdq = floordiv_s(SPAN - 1 - cq, STRIDE);
            float ox = 0.f, oy = 0.f;
            #pragma unroll
            for (int r = 0; r < R_SPAN; r++) {
                const float wr = __shfl_sync(0xffffffffu, w, qh * 16 + r);
                const int iir = min(max(r - fdq - colT0, 0), CTILE - 1);
                const float2 vv = __half22float2(Vsh[iir][lane]);
                ox += wr * vv.x;
                oy += wr * vv.y;
            }
            __half2 hp;
            hp.x = __float2half(ox);
            hp.y = __float2half(oy);
            *(__half2*)(ctxh + (size_t)(b * Lq + cq) * GK + h * DIM_V + 2 * lane) = hp;
        }
    }
}

// ---------------------------------------------------------------------------
// Launch
// ---------------------------------------------------------------------------
extern "C" void kernel_launch(void* const* d_in, const int* in_sizes, int n_in,
                              void* d_out, int out_size) {
    const float* q    = (const float*)d_in[0];
    const float* k    = (const float*)d_in[1];
    const float* v    = (const float*)d_in[2];
    const float* Wq   = (const float*)d_in[3];
    const float* Wk   = (const float*)d_in[4];
    const float* Wv   = (const float*)d_in[5];
    const float* Wout = (const float*)d_in[6];
    float* out = (float*)d_out;

    const int Lq  = in_sizes[0] / (BATCH * DMODEL);   // 4096
    const int Lkv = in_sizes[1] / (BATCH * DMODEL);   // 1024
    const int Mq  = BATCH * Lq;    // 8192
    const int Mkv = BATCH * Lkv;   // 2048

    __half *gAb, *gKb, *gVb, *gWb, *gQh, *gKh, *gVh;
    cudaGetSymbolAddress((void**)&gAb, g_Ab);
    cudaGetSymbolAddress((void**)&gKb, g_Kb);
    cudaGetSymbolAddress((void**)&gVb, g_Vb);
    cudaGetSymbolAddress((void**)&gWb, g_Wb4);
    cudaGetSymbolAddress((void**)&gQh, g_Qh);
    cudaGetSymbolAddress((void**)&gKh, g_Kh);
    cudaGetSymbolAddress((void**)&gVh, g_Vh);

    cudaFuncSetAttribute(gemm_qkv, cudaFuncAttributeMaxDynamicSharedMemorySize, GEMM_SMEM);
    cudaFuncSetAttribute(gemm_one, cudaFuncAttributeMaxDynamicSharedMemorySize, GEMM_SMEM);

    // 1. fused conversions: activations + all 4 weight transposes
    const int nact = ((Mq + 2 * Mkv) * 128 + 255) / 256;
    prep_all<<<nact + 1024, 256>>>((const float4*)q, (const float4*)k, (const float4*)v,
                                   Wq, Wk, Wv, Wout, gAb, gKb, gVb, gWb, Mq, Mkv);

    // 2. fused Q/K/V projection GEMM -> fp16 outputs
    gemm_qkv<<<384, 256, GEMM_SMEM>>>(gAb, gKb, gVb, gWb, gQh, gKh, gVh);

    // 3. sparse attention (all-fp16 I/O), writes ctx into gAb
    sparse_attn_v5<<<dim3(Lq / QBLK, BATCH * HEAD_NUM), 256>>>(gQh, gKh, gVh, gAb, Lq, Lkv);

    // 4. out projection -> fp32 d_out
    gemm_one<<<dim3(4, Mq / 128), 256, GEMM_SMEM>>>(gAb, gWb + 3 * (size_t)WSTRIDE, out);
}

// round 13
// speedup vs baseline: 7.1423x; 1.0065x over previous
#include <cuda_runtime.h>
#include <cuda_fp16.h>
#include <cstdint>

#define HEAD_NUM 8
#define DIM_QK 64
#define DIM_V 64
#define SPAN 64
#define STRIDE 4
#define R_SPAN 16

#define BATCH 2
#define MAX_LQ 4096
#define MAX_LKV 1024
#define DMODEL 512
#define GK 512           // single-rounded fp16 GEMM
#define CHUNKS 8         // GK / 64
#define WSTRIDE (DMODEL * GK)

// ---------------------------------------------------------------------------
// Scratch (no cudaMalloc allowed)
// ---------------------------------------------------------------------------
__device__ __align__(16) __half g_Ab[BATCH * MAX_LQ * GK];    // q-act fp16, then ctx fp16
__device__ __align__(16) __half g_Kb[BATCH * MAX_LKV * GK];   // k-act fp16
__device__ __align__(16) __half g_Vb[BATCH * MAX_LKV * GK];   // v-act fp16
__device__ __align__(16) __half g_Wb4[4 * WSTRIDE];           // 4 weights (transposed) fp16
__device__ __align__(16) __half g_Qh[BATCH * MAX_LQ * DMODEL];
__device__ __align__(16) __half g_Kh[BATCH * MAX_LKV * DMODEL];
__device__ __align__(16) __half g_Vh[BATCH * MAX_LKV * DMODEL];

// ---------------------------------------------------------------------------
// Baseline-target PTX helpers
// ---------------------------------------------------------------------------
__device__ __forceinline__ uint32_t smem_u32(const void* p) {
    uint32_t a;
    asm("{ .reg .u64 t; cvta.to.shared.u64 t, %1; cvt.u32.u64 %0, t; }" : "=r"(a) : "l"(p));
    return a;
}
__device__ __forceinline__ void cp_async16(uint32_t saddr, const void* gaddr) {
    asm volatile("cp.async.cg.shared.global [%0], [%1], 16;" :: "r"(saddr), "l"(gaddr));
}
__device__ __forceinline__ void cp_commit() { asm volatile("cp.async.commit_group;" ::: "memory"); }
__device__ __forceinline__ void cp_wait1() { asm volatile("cp.async.wait_group 1;" ::: "memory"); }
__device__ __forceinline__ void cp_wait0() { asm volatile("cp.async.wait_group 0;" ::: "memory"); }
__device__ __forceinline__ void ldm_x4(uint32_t* r, uint32_t addr) {
    asm volatile("ldmatrix.sync.aligned.m8n8.x4.shared.b16 {%0,%1,%2,%3}, [%4];"
                 : "=r"(r[0]), "=r"(r[1]), "=r"(r[2]), "=r"(r[3]) : "r"(addr));
}
__device__ __forceinline__ void ldm_x2(uint32_t* r, uint32_t addr) {
    asm volatile("ldmatrix.sync.aligned.m8n8.x2.shared.b16 {%0,%1}, [%2];"
                 : "=r"(r[0]), "=r"(r[1]) : "r"(addr));
}
__device__ __forceinline__ void mma_f16(float* c, const uint32_t* a, const uint32_t* b) {
    asm volatile("mma.sync.aligned.m16n8k16.row.col.f32.f16.f16.f32 "
                 "{%0,%1,%2,%3}, {%4,%5,%6,%7}, {%8,%9}, {%0,%1,%2,%3};"
                 : "+f"(c[0]), "+f"(c[1]), "+f"(c[2]), "+f"(c[3])
                 : "r"(a[0]), "r"(a[1]), "r"(a[2]), "r"(a[3]), "r"(b[0]), "r"(b[1]));
}
__device__ __forceinline__ uint32_t sw128(uint32_t off) { return off ^ ((off >> 3) & 0x70); }

// ---------------------------------------------------------------------------
// GEMM tile worker: CTA 128x64, 8 warps (4x2), warp tile 32x32.
// 3-stage cp.async pipeline. Stage = A 16KB + B 8KB = 24KB; total 72KB.
// __launch_bounds__(256, 2) -> regs<=128 -> >=2 CTAs/SM.
// ---------------------------------------------------------------------------
#define STAGE_BYTES 24576u
#define GEMM_SMEM (3 * STAGE_BYTES)

__device__ __forceinline__ void issue_chunk(const __half* __restrict__ A,
                                            const __half* __restrict__ Bt,
                                            uint32_t sb, int row0, int col0,
                                            int chunk, int stage, int tid) {
    const int k0 = chunk * 64;
    const uint32_t aoff = stage * STAGE_BYTES;
    const uint32_t boff = aoff + 16384u;
    #pragma unroll
    for (int p = 0; p < 4; p++) {
        const int idx = tid + p * 256;        // 0..1023 : A 128 rows x 8
        const int r = idx >> 3;
        const int c8 = idx & 7;
        const uint32_t sw = sw128((uint32_t)(r * 128 + c8 * 16));
        cp_async16(sb + aoff + sw, A + (size_t)(row0 + r) * GK + k0 + c8 * 8);
    }
    #pragma unroll
    for (int p = 0; p < 2; p++) {
        const int idx = tid + p * 256;        // 0..511 : B 64 rows x 8
        const int r = idx >> 3;
        const int c8 = idx & 7;
        const uint32_t sw = sw128((uint32_t)(r * 128 + c8 * 16));
        cp_async16(sb + boff + sw, Bt + (size_t)(col0 + r) * GK + k0 + c8 * 8);
    }
    cp_commit();
}

template <bool HOUT>
__device__ __forceinline__ void gemm_tile(const __half* __restrict__ A,
                                          const __half* __restrict__ Bt,
                                          void* __restrict__ Cp,
                                          int row0, int col0, uint32_t sb, int tid) {
    const int wid = tid >> 5, lane = tid & 31;
    const int warpM = wid >> 1;      // 0..3 (32 rows each)
    const int warpN = wid & 1;       // 0..1 (32 cols each)

    float acc[2][4][4];
    #pragma unroll
    for (int mi = 0; mi < 2; mi++)
        #pragma unroll
        for (int ni = 0; ni < 4; ni++)
            #pragma unroll
            for (int j = 0; j < 4; j++) acc[mi][ni][j] = 0.f;

    const int a_row_in_warp = lane & 15;
    const int a_khalf = (lane >> 4) & 1;
    const int b_row_in_tile = lane & 7;
    const int b_khalf = (lane >> 3) & 1;

    issue_chunk(A, Bt, sb, row0, col0, 0, 0, tid);
    issue_chunk(A, Bt, sb, row0, col0, 1, 1, tid);

    int stage = 0, nstage = 2;
    for (int i = 0; i < CHUNKS; i++) {
        if (i + 1 < CHUNKS) cp_wait1(); else cp_wait0();
        __syncthreads();

        if (i + 2 < CHUNKS) {
            issue_chunk(A, Bt, sb, row0, col0, i + 2, nstage, tid);
            nstage = (nstage + 1 == 3) ? 0 : nstage + 1;
        }

        const uint32_t aoff = stage * STAGE_BYTES;
        const uint32_t boff = aoff + 16384u;
        #pragma unroll
        for (int kk = 0; kk < 4; kk++) {
            uint32_t afrag[2][4], bfrag[4][2];
            #pragma unroll
            for (int mi = 0; mi < 2; mi++) {
                const int r = warpM * 32 + mi * 16 + a_row_in_warp;
                ldm_x4(afrag[mi], sb + aoff + sw128((uint32_t)(r * 128 + kk * 32 + a_khalf * 16)));
            }
            #pragma unroll
            for (int ni = 0; ni < 4; ni++) {
                const int r = warpN * 32 + ni * 8 + b_row_in_tile;
                ldm_x2(bfrag[ni], sb + boff + sw128((uint32_t)(r * 128 + kk * 32 + b_khalf * 16)));
            }
            #pragma unroll
            for (int mi = 0; mi < 2; mi++)
                #pragma unroll
                for (int ni = 0; ni < 4; ni++)
                    mma_f16(acc[mi][ni], afrag[mi], bfrag[ni]);
        }
        stage = (stage + 1 == 3) ? 0 : stage + 1;
    }

    const int erow = lane >> 2;
    const int ecol = 2 * (lane & 3);
    #pragma unroll
    for (int mi = 0; mi < 2; mi++) {
        #pragma unroll
        for (int ni = 0; ni < 4; ni++) {
            const int r = row0 + warpM * 32 + mi * 16 + erow;
            const int c = col0 + warpN * 32 + ni * 8 + ecol;
            if (HOUT) {
                __half* C = (__half*)Cp;
                *(__half2*)(C + (size_t)r * DMODEL + c) =
                    __floats2half2_rn(acc[mi][ni][0], acc[mi][ni][1]);
                *(__half2*)(C + (size_t)(r + 8) * DMODEL + c) =
                    __floats2half2_rn(acc[mi][ni][2], acc[mi][ni][3]);
            } else {
                float* C = (float*)Cp;
                *(float2*)(C + (size_t)r * DMODEL + c) = make_float2(acc[mi][ni][0], acc[mi][ni][1]);
                *(float2*)(C + (size_t)(r + 8) * DMODEL + c) = make_float2(acc[mi][ni][2], acc[mi][ni][3]);
            }
        }
    }
}

// Fused Q/K/V projection: 512 + 128 + 128 tiles of 128x64
__global__ __launch_bounds__(256, 2) void gemm_qkv(const __half* __restrict__ Aq,
                                                   const __half* __restrict__ Ak,
                                                   const __half* __restrict__ Av,
                                                   const __half* __restrict__ Wb,
                                                   __half* __restrict__ Cq,
                                                   __half* __restrict__ Ck,
                                                   __half* __restrict__ Cv) {
    extern __shared__ __align__(1024) char smem[];
    int t = blockIdx.x;
    const __half *A, *B;
    __half* C;
    if (t < 512) { A = Aq; B = Wb; C = Cq; }
    else if (t < 640) { t -= 512; A = Ak; B = Wb + WSTRIDE; C = Ck; }
    else { t -= 640; A = Av; B = Wb + 2 * WSTRIDE; C = Cv; }
    gemm_tile<true>(A, B, C, (t >> 3) * 128, (t & 7) * 64, smem_u32(smem), threadIdx.x);
}

__global__ __launch_bounds__(256, 2) void gemm_one(const __half* __restrict__ A,
                                                   const __half* __restrict__ Bt,
                                                   float* __restrict__ C) {
    extern __shared__ __align__(1024) char smem[];
    gemm_tile<false>(A, Bt, C, blockIdx.y * 128, blockIdx.x * 64, smem_u32(smem), threadIdx.x);
}

// ---------------------------------------------------------------------------
// prep_all: fused activation fp16 conversion + weight transpose/convert.
// ---------------------------------------------------------------------------
struct __align__(8) hf4 { __half a, b, c, d; };

__global__ __launch_bounds__(256) void prep_all(const float4* __restrict__ q,
                                                const float4* __restrict__ k,
                                                const float4* __restrict__ v,
                                                const float* __restrict__ W0,
                                                const float* __restrict__ W1,
                                                const float* __restrict__ W2,
                                                const float* __restrict__ W3,
                                                __half* __restrict__ outq,
                                                __half* __restrict__ outk,
                                                __half* __restrict__ outv,
                                                __half* __restrict__ Wb,
                                                int Mq, int Mkv) {
    __shared__ float tbuf[32][33];
    const int nq = Mq * 128, nkv = Mkv * 128;
    const int nact = (nq + 2 * nkv + 255) / 256;
    const int tid = threadIdx.x;

    if ((int)blockIdx.x < nact) {
        const int gid = blockIdx.x * 256 + tid;
        const float4* src;
        __half* out;
        int loc;
        if (gid < nq) { src = q; out = outq; loc = gid; }
        else if (gid < nq + nkv) { src = k; out = outk; loc = gid - nq; }
        else if (gid < nq + 2 * nkv) { src = v; out = outv; loc = gid - nq - nkv; }
        else return;
        float4 x = src[loc];
        hf4 hv;
        hv.a = __float2half(x.x); hv.b = __float2half(x.y);
        hv.c = __float2half(x.z); hv.d = __float2half(x.w);
        *(hf4*)(out + (size_t)loc * 4) = hv;
    } else {
        int t = blockIdx.x - nact;          // 0..1023
        const int z = t >> 8;
        const int tt = t & 255;
        const int k0 = (tt >> 4) * 32, n0 = (tt & 15) * 32;
        const float* W = (z == 0) ? W0 : (z == 1) ? W1 : (z == 2) ? W2 : W3;
        __half* outW = Wb + (size_t)z * WSTRIDE;
        const int r0 = tid >> 5, cc = tid & 31;
        #pragma unroll
        for (int j = 0; j < 4; j++)
            tbuf[r0 + j * 8][cc] = W[(size_t)(k0 + r0 + j * 8) * DMODEL + n0 + cc];
        __syncthreads();
        #pragma unroll
        for (int j = 0; j < 4; j++)
            outW[(size_t)(n0 + r0 + j * 8) * GK + k0 + cc] = __float2half(tbuf[cc][r0 + j * 8]);
    }
}

// ---------------------------------------------------------------------------
// Sparse attention v5 (unchanged from R12): all-fp16 I/O.
// ---------------------------------------------------------------------------
#define QBLK 64
#define CTILE 32
#define KSTRIDE 36

__device__ __forceinline__ int floordiv_s(int a, int d) {
    return (a >= 0) ? (a / d) : -((-a + d - 1) / d);
}

__global__ __launch_bounds__(256) void sparse_attn_v5(const __half* __restrict__ Qh,
                                                      const __half* __restrict__ Kh,
                                                      const __half* __restrict__ Vh,
                                                      __half* __restrict__ ctxh,
                                                      int Lq, int Lkv) {
    __shared__ __align__(16) __half2 Ksh[CTILE][KSTRIDE];
    __shared__ __align__(16) __half2 Vsh[CTILE][32];

    const int bh = blockIdx.y;
    const int b = bh / HEAD_NUM;
    const int h = bh % HEAD_NUM;
    const int c0 = blockIdx.x * QBLK;
    const int tid = threadIdx.x;
    const int wid = tid >> 5, lane = tid & 31;
    const int rlane = lane & 15;
    const int half = lane >> 4;

    const int colT0 = max(0, c0 / STRIDE - (R_SPAN - 1));

    {
        const int col = tid >> 3, d8 = tid & 7;
        if (colT0 + col < Lkv) {
            const uint4 kv = __ldg((const uint4*)(Kh + ((size_t)(b * Lkv + colT0 + col) * DMODEL) + h * 64 + d8 * 8));
            *(uint4*)&Ksh[col][d8 * 4] = kv;
        }
    }
    {
        const int col = tid >> 3, l8 = tid & 7;
        if (colT0 + col < Lkv) {
            const uint4 vv = __ldg((const uint4*)(Vh + ((size_t)(b * Lkv + colT0 + col) * DMODEL) + h * 64 + l8 * 8));
            *(uint4*)&Vsh[col][l8 * 4] = vv;
        }
    }
    __syncthreads();

    #pragma unroll
    for (int step = 0; step < 4; step++) {
        const int cbase = c0 + wid * 8 + step * 2;
        const int c = cbase + half;

        const int fd = floordiv_s(SPAN - 1 - c, STRIDE);
        const int col = rlane - fd;
        const int row = c - STRIDE * col;
        const bool valid = (row >= 0) && (row < SPAN) && (col >= 0) && (col < Lkv);
        const int ii = min(max(col - colT0, 0), CTILE - 1);

        const uint4* Qrow = (const uint4*)(Qh + ((size_t)(b * Lq + c) * DMODEL) + h * 64);
        float acc = 0.f;
        #pragma unroll
        for (int j8 = 0; j8 < 8; j8++) {
            const uint4 qp = __ldg(Qrow + j8);
            const uint4 kp = *(const uint4*)&Ksh[ii][j8 * 4];
            const float2 q0 = __half22float2(*(const __half2*)&qp.x);
            const float2 q1 = __half22float2(*(const __half2*)&qp.y);
            const float2 q2 = __half22float2(*(const __half2*)&qp.z);
            const float2 q3 = __half22float2(*(const __half2*)&qp.w);
            const float2 k0 = __half22float2(*(const __half2*)&kp.x);
            const float2 k1 = __half22float2(*(const __half2*)&kp.y);
            const float2 k2 = __half22float2(*(const __half2*)&kp.z);
            const float2 k3 = __half22float2(*(const __half2*)&kp.w);
            acc += q0.x * k0.x + q0.y * k0.y + q1.x * k1.x + q1.y * k1.y;
            acc += q2.x * k2.x + q2.y * k2.y + q3.x * k3.x + q3.y * k3.y;
        }
        const float sc = valid ? acc * 0.125f : -1e30f;

        float m = sc;
        #pragma unroll
        for (int off = 8; off > 0; off >>= 1)
            m = fmaxf(m, __shfl_xor_sync(0xffffffffu, m, off));
        const float e = valid ? __expf(sc - m) : 0.f;
        float s = e;
        #pragma unroll
        for (int off = 8; off > 0; off >>= 1)
            s += __shfl_xor_sync(0xffffffffu, s, off);
        const float w = e / s;

        #pragma unroll
        for (int qh = 0; qh < 2; qh++) {
            const int cq = cbase + qh;
            const int fdq = floordiv_s(SPAN - 1 - cq, STRIDE);
            float ox = 0.f, oy = 0.f;
            #pragma unroll
            for (int r = 0; r < R_SPAN; r++) {
                const float wr = __shfl_sync(0xffffffffu, w, qh * 16 + r);
                const int iir = min(max(r - fdq - colT0, 0), CTILE - 1);
                const float2 vv = __half22float2(Vsh[iir][lane]);
                ox += wr * vv.x;
                oy += wr * vv.y;
            }
            __half2 hp;
            hp.x = __float2half(ox);
            hp.y = __float2half(oy);
            *(__half2*)(ctxh + (size_t)(b * Lq + cq) * GK + h * DIM_V + 2 * lane) = hp;
        }
    }
}

// ---------------------------------------------------------------------------
// Launch
// ---------------------------------------------------------------------------
extern "C" void kernel_launch(void* const* d_in, const int* in_sizes, int n_in,
                              void* d_out, int out_size) {
    const float* q    = (const float*)d_in[0];
    const float* k    = (const float*)d_in[1];
    const float* v    = (const float*)d_in[2];
    const float* Wq   = (const float*)d_in[3];
    const float* Wk   = (const float*)d_in[4];
    const float* Wv   = (const float*)d_in[5];
    const float* Wout = (const float*)d_in[6];
    float* out = (float*)d_out;

    const int Lq  = in_sizes[0] / (BATCH * DMODEL);   // 4096
    const int Lkv = in_sizes[1] / (BATCH * DMODEL);   // 1024
    const int Mq  = BATCH * Lq;    // 8192
    const int Mkv = BATCH * Lkv;   // 2048

    __half *gAb, *gKb, *gVb, *gWb, *gQh, *gKh, *gVh;
    cudaGetSymbolAddress((void**)&gAb, g_Ab);
    cudaGetSymbolAddress((void**)&gKb, g_Kb);
    cudaGetSymbolAddress((void**)&gVb, g_Vb);
    cudaGetSymbolAddress((void**)&gWb, g_Wb4);
    cudaGetSymbolAddress((void**)&gQh, g_Qh);
    cudaGetSymbolAddress((void**)&gKh, g_Kh);
    cudaGetSymbolAddress((void**)&gVh, g_Vh);

    cudaFuncSetAttribute(gemm_qkv, cudaFuncAttributeMaxDynamicSharedMemorySize, GEMM_SMEM);
    cudaFuncSetAttribute(gemm_one, cudaFuncAttributeMaxDynamicSharedMemorySize, GEMM_SMEM);

    // 1. fused conversions
    const int nact = ((Mq + 2 * Mkv) * 128 + 255) / 256;
    prep_all<<<nact + 1024, 256>>>((const float4*)q, (const float4*)k, (const float4*)v,
                                   Wq, Wk, Wv, Wout, gAb, gKb, gVb, gWb, Mq, Mkv);

    // 2. fused Q/K/V projection GEMM (128x64 tiles: 512 + 128 + 128)
    gemm_qkv<<<768, 256, GEMM_SMEM>>>(gAb, gKb, gVb, gWb, gQh, gKh, gVh);

    // 3. sparse attention
    sparse_attn_v5<<<dim3(Lq / QBLK, BATCH * HEAD_NUM), 256>>>(gQh, gKh, gVh, gAb, Lq, Lkv);

    // 4. out projection -> fp32 d_out (64-col tiles: 8 x 64 grid)
    gemm_one<<<dim3(8, Mq / 128), 256, GEMM_SMEM>>>(gAb, gWb + 3 * (size_t)WSTRIDE, out);
}